// round 4
// baseline (speedup 1.0000x reference)
#include <cuda_runtime.h>
#include <math.h>

// Problem dims (fixed by the dataset)
#define E_   8
#define B_   8
#define S_   512
#define D_   768
#define H_   12
#define DH_  64
#define DFF_ 3072
#define QKVW 2304   // H_ * 3 * DH_

#define SCALE_F 0.036084391824351615f   // D_^-0.5

// ---------------------------------------------------------------------------
// Scratch: __device__ globals (no cudaMalloc allowed)
// ---------------------------------------------------------------------------
static __device__ float g_qkv[(size_t)E_ * B_ * S_ * QKVW];  // [e][b*S+s][h*192+k]
static __device__ float g_ctx[(size_t)E_ * B_ * S_ * D_];    // [e][t][h*64+d]
static __device__ float g_att[(size_t)E_ * B_ * S_ * D_];    // dense out (pre-residual)
static __device__ float g_feat[E_ * B_ * D_];
static __device__ int   g_sel[B_];
static __device__ float g_h1 [(size_t)B_ * S_ * D_];
static __device__ float g_mid[(size_t)B_ * S_ * DFF_];
static __device__ float g_ffn[(size_t)B_ * S_ * D_];

// ---------------------------------------------------------------------------
// Generic C = A * W^T (+bias)(+gelu) GEMM.
// A: M x K row-major, W: N x K row-major, C: M x N row-major.
// Per blockIdx.z: A += z*Az, C += z*Cz, weight index w = sel ? sel[z] : z.
// Tile 128x128x16, 256 threads, 8x8 per thread. All dims divisible (asserted by use).
// ---------------------------------------------------------------------------
template<bool GELU, bool HASBIAS>
__global__ __launch_bounds__(256)
void gemm_kernel(const float* __restrict__ A, const float* __restrict__ W,
                 const float* __restrict__ bias, float* __restrict__ C,
                 int M, int N, int K,
                 long Az, long Wz, long biasz, long Cz,
                 const int* __restrict__ sel)
{
    const int z = blockIdx.z;
    const int w = sel ? sel[z] : z;
    A += (long)z * Az;
    W += (long)w * Wz;
    if (HASBIAS) bias += (long)w * biasz;
    C += (long)z * Cz;

    __shared__ float As[16][132];
    __shared__ float Bs[16][132];

    const int tid = threadIdx.x;
    const int m0 = blockIdx.y * 128;
    const int n0 = blockIdx.x * 128;
    const int lc = (tid & 3) * 4;   // k offset of this thread's float4
    const int lr = tid >> 2;        // row 0..63 (+64 on second iter)
    const int tx = tid & 15;
    const int ty = tid >> 4;

    float acc[8][8];
    #pragma unroll
    for (int i = 0; i < 8; i++)
        #pragma unroll
        for (int j = 0; j < 8; j++) acc[i][j] = 0.f;

    for (int k0 = 0; k0 < K; k0 += 16) {
        #pragma unroll
        for (int i = 0; i < 2; i++) {
            int r = lr + i * 64;
            float4 va = *(const float4*)&A[(long)(m0 + r) * K + k0 + lc];
            As[lc + 0][r] = va.x; As[lc + 1][r] = va.y;
            As[lc + 2][r] = va.z; As[lc + 3][r] = va.w;
            float4 vb = *(const float4*)&W[(long)(n0 + r) * K + k0 + lc];
            Bs[lc + 0][r] = vb.x; Bs[lc + 1][r] = vb.y;
            Bs[lc + 2][r] = vb.z; Bs[lc + 3][r] = vb.w;
        }
        __syncthreads();
        #pragma unroll
        for (int kk = 0; kk < 16; kk++) {
            float a[8], b[8];
            *(float4*)&a[0] = *(const float4*)&As[kk][ty * 8];
            *(float4*)&a[4] = *(const float4*)&As[kk][ty * 8 + 4];
            *(float4*)&b[0] = *(const float4*)&Bs[kk][tx * 8];
            *(float4*)&b[4] = *(const float4*)&Bs[kk][tx * 8 + 4];
            #pragma unroll
            for (int i = 0; i < 8; i++)
                #pragma unroll
                for (int j = 0; j < 8; j++)
                    acc[i][j] += a[i] * b[j];
        }
        __syncthreads();
    }

    #pragma unroll
    for (int i = 0; i < 8; i++) {
        const long m = m0 + ty * 8 + i;
        #pragma unroll
        for (int j = 0; j < 8; j++) {
            const int n = n0 + tx * 8 + j;
            float v = acc[i][j];
            if (HASBIAS) v += bias[n];
            if (GELU)    v = 0.5f * v * (1.0f + erff(v * 0.7071067811865476f));
            C[m * N + n] = v;
        }
    }
}

// ---------------------------------------------------------------------------
// Flash-attention per (e,b,h, query-tile of 64). 128 threads: 2 threads/row.
// Q row held in registers; K/V tiles (64x64) in smem (broadcast reads).
// ---------------------------------------------------------------------------
__global__ __launch_bounds__(128)
void attn_kernel(const int* __restrict__ mask)
{
    const int qt  = blockIdx.x;        // 0..7
    const int h   = blockIdx.y;        // 0..11
    const int eb  = blockIdx.z;        // e*8 + b
    const int b   = eb & 7;
    const int tid = threadIdx.x;
    const int row = tid >> 1;
    const int c0  = (tid & 1) * 32;    // this thread's half (keys / dims / output)

    const long rowbase = (long)eb * S_ * QKVW + h * 192;

    __shared__ float Ks[64][68];
    __shared__ float Vs[64][68];
    __shared__ int   msk[64];

    float q[64];
    {
        const float* qp = g_qkv + rowbase + (long)(qt * 64 + row) * QKVW;
        #pragma unroll
        for (int i = 0; i < 16; i++) {
            float4 v = *(const float4*)(qp + 4 * i);
            q[4*i] = v.x; q[4*i+1] = v.y; q[4*i+2] = v.z; q[4*i+3] = v.w;
        }
    }

    float o[32];
    #pragma unroll
    for (int d = 0; d < 32; d++) o[d] = 0.f;
    float m_run = -1e30f, l_run = 0.f;

    for (int kt = 0; kt < 8; kt++) {
        {
            const float* kp = g_qkv + rowbase + (long)(kt * 64 + row) * QKVW + 64 + c0;
            const float* vp = kp + 64;
            #pragma unroll
            for (int i = 0; i < 8; i++) {
                *(float4*)&Ks[row][c0 + 4 * i] = *(const float4*)(kp + 4 * i);
                *(float4*)&Vs[row][c0 + 4 * i] = *(const float4*)(vp + 4 * i);
            }
            if (tid < 64) msk[tid] = mask[b * S_ + kt * 64 + tid];
        }
        __syncthreads();

        float p[32];
        float mloc = -1e30f;
        #pragma unroll
        for (int jj = 0; jj < 32; jj++) {
            const int j = c0 + jj;
            float s = 0.f;
            #pragma unroll
            for (int d4 = 0; d4 < 16; d4++) {
                float4 kv = *(const float4*)&Ks[j][4 * d4];
                s += q[4*d4] * kv.x + q[4*d4+1] * kv.y
                   + q[4*d4+2] * kv.z + q[4*d4+3] * kv.w;
            }
            s *= SCALE_F;
            if (msk[j] == 0) s = -1e30f;
            p[jj] = s;
            mloc = fmaxf(mloc, s);
        }
        float mtile = fmaxf(mloc, __shfl_xor_sync(0xffffffffu, mloc, 1));
        float m_new = fmaxf(m_run, mtile);
        float corr  = __expf(m_run - m_new);
        float lloc = 0.f;
        #pragma unroll
        for (int jj = 0; jj < 32; jj++) { p[jj] = __expf(p[jj] - m_new); lloc += p[jj]; }
        l_run = l_run * corr + lloc + __shfl_xor_sync(0xffffffffu, lloc, 1);
        #pragma unroll
        for (int d = 0; d < 32; d++) o[d] *= corr;

        #pragma unroll
        for (int jj = 0; jj < 32; jj++) {
            float pa = p[jj];
            float pb = __shfl_xor_sync(0xffffffffu, pa, 1);
            const int ja = c0 + jj;
            const int jb = (c0 ^ 32) + jj;
            #pragma unroll
            for (int d4 = 0; d4 < 8; d4++) {
                float4 va = *(const float4*)&Vs[ja][c0 + 4 * d4];
                float4 vb = *(const float4*)&Vs[jb][c0 + 4 * d4];
                o[4*d4]   += pa * va.x + pb * vb.x;
                o[4*d4+1] += pa * va.y + pb * vb.y;
                o[4*d4+2] += pa * va.z + pb * vb.z;
                o[4*d4+3] += pa * va.w + pb * vb.w;
            }
        }
        m_run = m_new;
        __syncthreads();
    }

    const float inv = 1.f / l_run;
    float* op = g_ctx + ((long)eb * S_ + qt * 64 + row) * D_ + h * 64 + c0;
    #pragma unroll
    for (int d4 = 0; d4 < 8; d4++) {
        float4 v;
        v.x = o[4*d4] * inv; v.y = o[4*d4+1] * inv;
        v.z = o[4*d4+2] * inv; v.w = o[4*d4+3] * inv;
        *(float4*)(op + 4 * d4) = v;
    }
}

// ---------------------------------------------------------------------------
// feat[e,b,:] = mean over S of g_att[e,b,:,:]
// ---------------------------------------------------------------------------
__global__ __launch_bounds__(768)
void feat_kernel()
{
    const int eb = blockIdx.x;
    const int d  = threadIdx.x;
    const float* p = g_att + (long)eb * S_ * D_ + d;
    float s = 0.f;
    #pragma unroll 8
    for (int t = 0; t < S_; t++) s += p[(long)t * D_];
    g_feat[eb * D_ + d] = s * (1.0f / (float)S_);
}

// ---------------------------------------------------------------------------
// sel[b] = argmin_e ||feat[e,b] - centers[e]||  (compare squared distances)
// ---------------------------------------------------------------------------
__global__ __launch_bounds__(256)
void route_kernel(const float* __restrict__ centers)
{
    const int b = blockIdx.x, tid = threadIdx.x;
    __shared__ float red[256];
    float best = 3.4e38f;
    int   bi   = 0;
    for (int e = 0; e < E_; e++) {
        float s = 0.f;
        const float* fp = g_feat + (e * B_ + b) * D_;
        const float* cp = centers + e * D_;
        for (int d = tid; d < D_; d += 256) {
            float df = fp[d] - cp[d];
            s += df * df;
        }
        red[tid] = s; __syncthreads();
        for (int st = 128; st > 0; st >>= 1) {
            if (tid < st) red[tid] += red[tid + st];
            __syncthreads();
        }
        if (tid == 0 && red[0] < best) { best = red[0]; bi = e; }
        __syncthreads();
    }
    if (tid == 0) g_sel[b] = bi;
}

// ---------------------------------------------------------------------------
// h1 = LN(att[sel[b]] + x) * g1[sel] + b1[sel]
// ---------------------------------------------------------------------------
__global__ __launch_bounds__(256)
void add_ln1_kernel(const float* __restrict__ x,
                    const float* __restrict__ gma, const float* __restrict__ bta)
{
    const int t = blockIdx.x;           // b*512 + s
    const int b = t >> 9;
    const int e = g_sel[b];
    const int tid = threadIdx.x;
    const float* ap = g_att + ((long)e * (B_ * S_) + t) * D_;
    const float* xp = x + (long)t * D_;
    __shared__ float red[256];

    float v0 = ap[tid]       + xp[tid];
    float v1 = ap[tid + 256] + xp[tid + 256];
    float v2 = ap[tid + 512] + xp[tid + 512];

    red[tid] = v0 + v1 + v2; __syncthreads();
    for (int st = 128; st > 0; st >>= 1) { if (tid < st) red[tid] += red[tid + st]; __syncthreads(); }
    const float mean = red[0] * (1.0f / (float)D_);
    __syncthreads();
    float d0 = v0 - mean, d1 = v1 - mean, d2 = v2 - mean;
    red[tid] = d0*d0 + d1*d1 + d2*d2; __syncthreads();
    for (int st = 128; st > 0; st >>= 1) { if (tid < st) red[tid] += red[tid + st]; __syncthreads(); }
    const float rstd = rsqrtf(red[0] * (1.0f / (float)D_) + 1e-12f);

    const float* g  = gma + e * D_;
    const float* bb = bta + e * D_;
    float* hp = g_h1 + (long)t * D_;
    hp[tid]       = d0 * rstd * g[tid]       + bb[tid];
    hp[tid + 256] = d1 * rstd * g[tid + 256] + bb[tid + 256];
    hp[tid + 512] = d2 * rstd * g[tid + 512] + bb[tid + 512];
}

// ---------------------------------------------------------------------------
// out = LN(h1 + ffn) * g2[sel] + b2[sel]   -> d_out (B,S,D) float32
// ---------------------------------------------------------------------------
__global__ __launch_bounds__(256)
void ln2_kernel(const float* __restrict__ gma, const float* __restrict__ bta,
                float* __restrict__ out)
{
    const int t = blockIdx.x;
    const int b = t >> 9;
    const int e = g_sel[b];
    const int tid = threadIdx.x;
    const float* hp = g_h1  + (long)t * D_;
    const float* fp = g_ffn + (long)t * D_;
    __shared__ float red[256];

    float v0 = hp[tid]       + fp[tid];
    float v1 = hp[tid + 256] + fp[tid + 256];
    float v2 = hp[tid + 512] + fp[tid + 512];

    red[tid] = v0 + v1 + v2; __syncthreads();
    for (int st = 128; st > 0; st >>= 1) { if (tid < st) red[tid] += red[tid + st]; __syncthreads(); }
    const float mean = red[0] * (1.0f / (float)D_);
    __syncthreads();
    float d0 = v0 - mean, d1 = v1 - mean, d2 = v2 - mean;
    red[tid] = d0*d0 + d1*d1 + d2*d2; __syncthreads();
    for (int st = 128; st > 0; st >>= 1) { if (tid < st) red[tid] += red[tid + st]; __syncthreads(); }
    const float rstd = rsqrtf(red[0] * (1.0f / (float)D_) + 1e-12f);

    const float* g  = gma + e * D_;
    const float* bb = bta + e * D_;
    float* op = out + (long)t * D_;
    op[tid]       = d0 * rstd * g[tid]       + bb[tid];
    op[tid + 256] = d1 * rstd * g[tid + 256] + bb[tid + 256];
    op[tid + 512] = d2 * rstd * g[tid + 512] + bb[tid + 512];
}

// ---------------------------------------------------------------------------
extern "C" void kernel_launch(void* const* d_in, const int* in_sizes, int n_in,
                              void* d_out, int out_size)
{
    const float* x       = (const float*)d_in[0];
    const int*   mask    = (const int*)  d_in[1];
    const float* Wqkv    = (const float*)d_in[2];
    const float* Wd      = (const float*)d_in[3];
    const float* bd      = (const float*)d_in[4];
    const float* ln1g    = (const float*)d_in[5];
    const float* ln1b    = (const float*)d_in[6];
    const float* W1      = (const float*)d_in[7];
    const float* b1      = (const float*)d_in[8];
    const float* W2      = (const float*)d_in[9];
    const float* b2      = (const float*)d_in[10];
    const float* ln2g    = (const float*)d_in[11];
    const float* ln2b    = (const float*)d_in[12];
    const float* centers = (const float*)d_in[13];
    float* out = (float*)d_out;

    float *qkvp, *ctxp, *attp, *h1p, *midp, *ffnp;
    int* selp;
    cudaGetSymbolAddress((void**)&qkvp, g_qkv);
    cudaGetSymbolAddress((void**)&ctxp, g_ctx);
    cudaGetSymbolAddress((void**)&attp, g_att);
    cudaGetSymbolAddress((void**)&h1p,  g_h1);
    cudaGetSymbolAddress((void**)&midp, g_mid);
    cudaGetSymbolAddress((void**)&ffnp, g_ffn);
    cudaGetSymbolAddress((void**)&selp, g_sel);

    const int M = B_ * S_;   // 4096

    // 1. QKV for all experts: (4096 x 768) x (2304 x 768)^T per e
    gemm_kernel<false, false><<<dim3(QKVW / 128, M / 128, E_), 256>>>(
        x, Wqkv, nullptr, qkvp, M, QKVW, D_,
        0L, (long)QKVW * D_, 0L, (long)M * QKVW, nullptr);

    // 2. Attention for all (e,b,h)
    attn_kernel<<<dim3(S_ / 64, H_, E_ * B_), 128>>>(mask);

    // 3. attention.dense for all experts
    gemm_kernel<false, true><<<dim3(D_ / 128, M / 128, E_), 256>>>(
        ctxp, Wd, bd, attp, M, D_, D_,
        (long)M * D_, (long)D_ * D_, (long)D_, (long)M * D_, nullptr);

    // 4. routing features + hard routing
    feat_kernel<<<E_ * B_, 768>>>();
    route_kernel<<<B_, 256>>>(centers);

    // 5. post-attention LN (selected expert only)
    add_ln1_kernel<<<M, 256>>>(x, ln1g, ln1b);

    // 6. FFN (selected expert only): gelu(h1 @ W1^T + b1)
    gemm_kernel<true, true><<<dim3(DFF_ / 128, S_ / 128, B_), 256>>>(
        h1p, W1, b1, midp, S_, DFF_, D_,
        (long)S_ * D_, (long)DFF_ * D_, (long)DFF_, (long)S_ * DFF_, selp);

    // 7. mid @ W2^T + b2
    gemm_kernel<false, true><<<dim3(D_ / 128, S_ / 128, B_), 256>>>(
        midp, W2, b2, ffnp, S_, D_, DFF_,
        (long)S_ * DFF_, (long)D_ * DFF_, (long)D_, (long)S_ * D_, selp);

    // 8. final LN -> output
    ln2_kernel<<<M, 256>>>(ln2g, ln2b, out);
}

// round 9
// speedup vs baseline: 1.5308x; 1.5308x over previous
#include <cuda_runtime.h>
#include <math.h>

// Problem dims (fixed by the dataset)
#define E_   8
#define B_   8
#define S_   512
#define D_   768
#define H_   12
#define DH_  64
#define DFF_ 3072
#define QKVW 2304   // H_ * 3 * DH_

#define SCALE_F 0.036084391824351615f   // D_^-0.5

// ---------------------------------------------------------------------------
// Scratch: __device__ globals (no cudaMalloc allowed)
// ---------------------------------------------------------------------------
static __device__ float g_qkv [(size_t)E_ * B_ * S_ * QKVW];  // [e][b*S+s][h*192+k]
static __device__ float g_ctx [(size_t)E_ * B_ * S_ * D_];    // [e][t][h*64+d]
static __device__ float g_mctx[E_ * B_ * D_];                 // seq-mean of ctx
static __device__ float g_att [(size_t)B_ * S_ * D_];         // dense out, SELECTED expert
static __device__ float g_feat[E_ * B_ * D_];
static __device__ int   g_sel[B_];
static __device__ float g_h1 [(size_t)B_ * S_ * D_];
static __device__ float g_mid[(size_t)B_ * S_ * DFF_];
static __device__ float g_ffn[(size_t)B_ * S_ * D_];

// ---------------------------------------------------------------------------
// Helpers
// ---------------------------------------------------------------------------
__device__ __forceinline__ float f2tf32(float x) {
    unsigned u;
    asm("cvt.rna.tf32.f32 %0, %1;" : "=r"(u) : "f"(x));
    return __uint_as_float(u);
}

#define MMA_TF32(d, a0, a1, a2, a3, b0, b1)                                   \
    asm volatile("mma.sync.aligned.m16n8k8.row.col.f32.tf32.tf32.f32 "        \
                 "{%0,%1,%2,%3}, {%4,%5,%6,%7}, {%8,%9}, {%0,%1,%2,%3};"      \
                 : "+f"(d[0]), "+f"(d[1]), "+f"(d[2]), "+f"(d[3])             \
                 : "r"(a0), "r"(a1), "r"(a2), "r"(a3), "r"(b0), "r"(b1));

// ---------------------------------------------------------------------------
// Tensor-core GEMM: C = A * W^T (+bias)(+gelu), tf32 inputs / fp32 accum.
// A: M x K row-major, W: N x K row-major, C: M x N row-major.
// Per blockIdx.z: A += z*Az + (sel? sel[z]*Asel : 0); weight idx w = sel? sel[z] : z.
// Block tile 128x128x16, 256 threads (8 warps, each 64x32 = 4x4 m16n8 tiles).
//
// Smem layout: m-major with k-interleaved columns within each 16-wide chunk:
//   phys_col(k) = (k & 8) | ((k & 3) << 1) | ((k >> 2) & 1)
// so the fragment pairs (k=kc, k=kc+4) sit in adjacent 4B words -> LDS.64.
// ---------------------------------------------------------------------------
template<bool GELU, bool HASBIAS>
__global__ __launch_bounds__(256)
void mma_gemm(const float* __restrict__ A, const float* __restrict__ W,
              const float* __restrict__ bias, float* __restrict__ C,
              int M, int N, int K,
              long Az, long Asel, long Wz, long biasz, long Cz,
              const int* __restrict__ sel)
{
    const int z = blockIdx.z;
    const int w = sel ? sel[z] : z;
    A += (long)z * Az + (sel ? (long)w * Asel : 0L);
    W += (long)w * Wz;
    if (HASBIAS) bias += (long)w * biasz;
    C += (long)z * Cz;

    __shared__ float As[128][20];   // [m][phys_k], 16 used + pad
    __shared__ float Bs[128][20];   // [n][phys_k]

    const int tid  = threadIdx.x;
    const int m0   = blockIdx.y * 128;
    const int n0   = blockIdx.x * 128;
    const int warp = tid >> 5;
    const int lane = tid & 31;
    const int wm   = (warp & 1) * 64;     // warp row offset
    const int wn   = (warp >> 1) * 32;    // warp col offset
    const int g    = lane >> 2;           // groupID   0..7
    const int kc   = lane & 3;            // tid-in-grp 0..3

    float acc[4][4][4];
    #pragma unroll
    for (int i = 0; i < 4; i++)
        #pragma unroll
        for (int j = 0; j < 4; j++)
            #pragma unroll
            for (int q = 0; q < 4; q++) acc[i][j][q] = 0.f;

    // global->smem assignment
    const int lc = (tid & 3) * 4;    // k offset of this thread's float4
    const int lr = tid >> 2;         // row 0..63 (+64 second iter)
    // phys columns for the 4 scalars of the float4 (k = lc + q)
    int pc[4];
    #pragma unroll
    for (int q = 0; q < 4; q++) {
        int k = lc + q;
        pc[q] = (k & 8) | ((k & 3) << 1) | ((k >> 2) & 1);
    }

    for (int k0 = 0; k0 < K; k0 += 16) {
        #pragma unroll
        for (int i = 0; i < 2; i++) {
            const int r = lr + i * 64;
            float4 va = *(const float4*)&A[(long)(m0 + r) * K + k0 + lc];
            As[r][pc[0]] = f2tf32(va.x); As[r][pc[1]] = f2tf32(va.y);
            As[r][pc[2]] = f2tf32(va.z); As[r][pc[3]] = f2tf32(va.w);
            float4 vb = *(const float4*)&W[(long)(n0 + r) * K + k0 + lc];
            Bs[r][pc[0]] = f2tf32(vb.x); Bs[r][pc[1]] = f2tf32(vb.y);
            Bs[r][pc[2]] = f2tf32(vb.z); Bs[r][pc[3]] = f2tf32(vb.w);
        }
        __syncthreads();

        #pragma unroll
        for (int ks = 0; ks < 2; ks++) {
            const int kb = ks * 8 + 2 * kc;
            unsigned af[4][4], bf[4][2];
            #pragma unroll
            for (int i = 0; i < 4; i++) {
                const int r = wm + i * 16 + g;
                float2 a02 = *(const float2*)&As[r][kb];
                float2 a13 = *(const float2*)&As[r + 8][kb];
                af[i][0] = __float_as_uint(a02.x);
                af[i][1] = __float_as_uint(a13.x);
                af[i][2] = __float_as_uint(a02.y);
                af[i][3] = __float_as_uint(a13.y);
            }
            #pragma unroll
            for (int j = 0; j < 4; j++) {
                const int c = wn + j * 8 + g;
                float2 b01 = *(const float2*)&Bs[c][kb];
                bf[j][0] = __float_as_uint(b01.x);
                bf[j][1] = __float_as_uint(b01.y);
            }
            #pragma unroll
            for (int i = 0; i < 4; i++)
                #pragma unroll
                for (int j = 0; j < 4; j++)
                    MMA_TF32(acc[i][j], af[i][0], af[i][1], af[i][2], af[i][3],
                             bf[j][0], bf[j][1]);
        }
        __syncthreads();
    }

    // epilogue
    #pragma unroll
    for (int i = 0; i < 4; i++) {
        const long row0 = m0 + wm + i * 16 + g;
        #pragma unroll
        for (int j = 0; j < 4; j++) {
            const int col = n0 + wn + j * 8 + 2 * kc;
            float v0 = acc[i][j][0], v1 = acc[i][j][1];
            float v2 = acc[i][j][2], v3 = acc[i][j][3];
            if (HASBIAS) {
                float bb0 = bias[col], bb1 = bias[col + 1];
                v0 += bb0; v1 += bb1; v2 += bb0; v3 += bb1;
            }
            if (GELU) {
                v0 = 0.5f * v0 * (1.0f + erff(v0 * 0.7071067811865476f));
                v1 = 0.5f * v1 * (1.0f + erff(v1 * 0.7071067811865476f));
                v2 = 0.5f * v2 * (1.0f + erff(v2 * 0.7071067811865476f));
                v3 = 0.5f * v3 * (1.0f + erff(v3 * 0.7071067811865476f));
            }
            float2 lo = {v0, v1}, hi = {v2, v3};
            *(float2*)&C[row0 * N + col]       = lo;
            *(float2*)&C[(row0 + 8) * N + col] = hi;
        }
    }
}

// ---------------------------------------------------------------------------
// Flash-attention per (e,b,h, query-tile of 64). 128 threads: 2 threads/row.
// ---------------------------------------------------------------------------
__global__ __launch_bounds__(128)
void attn_kernel(const int* __restrict__ mask)
{
    const int qt  = blockIdx.x;        // 0..7
    const int h   = blockIdx.y;        // 0..11
    const int eb  = blockIdx.z;        // e*8 + b
    const int b   = eb & 7;
    const int tid = threadIdx.x;
    const int row = tid >> 1;
    const int c0  = (tid & 1) * 32;

    const long rowbase = (long)eb * S_ * QKVW + h * 192;

    __shared__ float Ks[64][68];
    __shared__ float Vs[64][68];
    __shared__ int   msk[64];

    float q[64];
    {
        const float* qp = g_qkv + rowbase + (long)(qt * 64 + row) * QKVW;
        #pragma unroll
        for (int i = 0; i < 16; i++) {
            float4 v = *(const float4*)(qp + 4 * i);
            q[4*i] = v.x; q[4*i+1] = v.y; q[4*i+2] = v.z; q[4*i+3] = v.w;
        }
    }

    float o[32];
    #pragma unroll
    for (int d = 0; d < 32; d++) o[d] = 0.f;
    float m_run = -1e30f, l_run = 0.f;

    for (int kt = 0; kt < 8; kt++) {
        {
            const float* kp = g_qkv + rowbase + (long)(kt * 64 + row) * QKVW + 64 + c0;
            const float* vp = kp + 64;
            #pragma unroll
            for (int i = 0; i < 8; i++) {
                *(float4*)&Ks[row][c0 + 4 * i] = *(const float4*)(kp + 4 * i);
                *(float4*)&Vs[row][c0 + 4 * i] = *(const float4*)(vp + 4 * i);
            }
            if (tid < 64) msk[tid] = mask[b * S_ + kt * 64 + tid];
        }
        __syncthreads();

        float p[32];
        float mloc = -1e30f;
        #pragma unroll
        for (int jj = 0; jj < 32; jj++) {
            const int j = c0 + jj;
            float s = 0.f;
            #pragma unroll
            for (int d4 = 0; d4 < 16; d4++) {
                float4 kv = *(const float4*)&Ks[j][4 * d4];
                s += q[4*d4] * kv.x + q[4*d4+1] * kv.y
                   + q[4*d4+2] * kv.z + q[4*d4+3] * kv.w;
            }
            s *= SCALE_F;
            if (msk[j] == 0) s = -1e30f;
            p[jj] = s;
            mloc = fmaxf(mloc, s);
        }
        float mtile = fmaxf(mloc, __shfl_xor_sync(0xffffffffu, mloc, 1));
        float m_new = fmaxf(m_run, mtile);
        float corr  = __expf(m_run - m_new);
        float lloc = 0.f;
        #pragma unroll
        for (int jj = 0; jj < 32; jj++) { p[jj] = __expf(p[jj] - m_new); lloc += p[jj]; }
        l_run = l_run * corr + lloc + __shfl_xor_sync(0xffffffffu, lloc, 1);
        #pragma unroll
        for (int d = 0; d < 32; d++) o[d] *= corr;

        #pragma unroll
        for (int jj = 0; jj < 32; jj++) {
            float pa = p[jj];
            float pb = __shfl_xor_sync(0xffffffffu, pa, 1);
            const int ja = c0 + jj;
            const int jb = (c0 ^ 32) + jj;
            #pragma unroll
            for (int d4 = 0; d4 < 8; d4++) {
                float4 va = *(const float4*)&Vs[ja][c0 + 4 * d4];
                float4 vb = *(const float4*)&Vs[jb][c0 + 4 * d4];
                o[4*d4]   += pa * va.x + pb * vb.x;
                o[4*d4+1] += pa * va.y + pb * vb.y;
                o[4*d4+2] += pa * va.z + pb * vb.z;
                o[4*d4+3] += pa * va.w + pb * vb.w;
            }
        }
        m_run = m_new;
        __syncthreads();
    }

    const float inv = 1.f / l_run;
    float* op = g_ctx + ((long)eb * S_ + qt * 64 + row) * D_ + h * 64 + c0;
    #pragma unroll
    for (int d4 = 0; d4 < 8; d4++) {
        float4 v;
        v.x = o[4*d4] * inv; v.y = o[4*d4+1] * inv;
        v.z = o[4*d4+2] * inv; v.w = o[4*d4+3] * inv;
        *(float4*)(op + 4 * d4) = v;
    }
}

// ---------------------------------------------------------------------------
// mctx[eb,:] = mean over S of g_ctx[eb,:,:]
// ---------------------------------------------------------------------------
__global__ __launch_bounds__(768)
void mean_ctx_kernel()
{
    const int eb = blockIdx.x;
    const int d  = threadIdx.x;
    const float* p = g_ctx + (long)eb * S_ * D_ + d;
    float s = 0.f;
    #pragma unroll 8
    for (int t = 0; t < S_; t++) s += p[(long)t * D_];
    g_mctx[eb * D_ + d] = s * (1.0f / (float)S_);
}

// ---------------------------------------------------------------------------
// feat[e,b,n] = mctx[e,b,:] . Wd[e,n,:] + bd[e,n]   (exactly mean_s(att))
// grid (nchunk=6, e=8), 256 threads: 8 warps x 16 rows, warp-reduced dots.
// ---------------------------------------------------------------------------
__global__ __launch_bounds__(256)
void featgemm_kernel(const float* __restrict__ Wd, const float* __restrict__ bd)
{
    const int e  = blockIdx.y;
    const int nc = blockIdx.x;
    const int tid = threadIdx.x, warp = tid >> 5, lane = tid & 31;

    __shared__ float mc[8][768];
    for (int i = tid; i < 8 * 768; i += 256)
        mc[i / 768][i % 768] = g_mctx[(e * 8 + i / 768) * D_ + i % 768];
    __syncthreads();

    for (int rr = 0; rr < 16; rr++) {
        const int n = nc * 128 + warp * 16 + rr;
        const float* wp = Wd + ((long)e * D_ + n) * D_;
        float wreg[24];
        #pragma unroll
        for (int j = 0; j < 24; j++) wreg[j] = wp[lane + 32 * j];
        #pragma unroll
        for (int b = 0; b < 8; b++) {
            float s = 0.f;
            #pragma unroll
            for (int j = 0; j < 24; j++) s += wreg[j] * mc[b][lane + 32 * j];
            #pragma unroll
            for (int off = 16; off > 0; off >>= 1)
                s += __shfl_xor_sync(0xffffffffu, s, off);
            if (lane == 0)
                g_feat[(e * 8 + b) * D_ + n] = s + bd[e * D_ + n];
        }
    }
}

// ---------------------------------------------------------------------------
// sel[b] = argmin_e ||feat[e,b] - centers[e]||
// ---------------------------------------------------------------------------
__global__ __launch_bounds__(256)
void route_kernel(const float* __restrict__ centers)
{
    const int b = blockIdx.x, tid = threadIdx.x;
    __shared__ float red[256];
    float best = 3.4e38f;
    int   bi   = 0;
    for (int e = 0; e < E_; e++) {
        float s = 0.f;
        const float* fp = g_feat + (e * B_ + b) * D_;
        const float* cp = centers + e * D_;
        for (int d = tid; d < D_; d += 256) {
            float df = fp[d] - cp[d];
            s += df * df;
        }
        red[tid] = s; __syncthreads();
        for (int st = 128; st > 0; st >>= 1) {
            if (tid < st) red[tid] += red[tid + st];
            __syncthreads();
        }
        if (tid == 0 && red[0] < best) { best = red[0]; bi = e; }
        __syncthreads();
    }
    if (tid == 0) g_sel[b] = bi;
}

// ---------------------------------------------------------------------------
// h1 = LN(att_sel + x) * g1[sel] + b1[sel]
// ---------------------------------------------------------------------------
__global__ __launch_bounds__(256)
void add_ln1_kernel(const float* __restrict__ x,
                    const float* __restrict__ gma, const float* __restrict__ bta)
{
    const int t = blockIdx.x;           // b*512 + s
    const int b = t >> 9;
    const int e = g_sel[b];
    const int tid = threadIdx.x;
    const float* ap = g_att + (long)t * D_;
    const float* xp = x + (long)t * D_;
    __shared__ float red[256];

    float v0 = ap[tid]       + xp[tid];
    float v1 = ap[tid + 256] + xp[tid + 256];
    float v2 = ap[tid + 512] + xp[tid + 512];

    red[tid] = v0 + v1 + v2; __syncthreads();
    for (int st = 128; st > 0; st >>= 1) { if (tid < st) red[tid] += red[tid + st]; __syncthreads(); }
    const float mean = red[0] * (1.0f / (float)D_);
    __syncthreads();
    float d0 = v0 - mean, d1 = v1 - mean, d2 = v2 - mean;
    red[tid] = d0*d0 + d1*d1 + d2*d2; __syncthreads();
    for (int st = 128; st > 0; st >>= 1) { if (tid < st) red[tid] += red[tid + st]; __syncthreads(); }
    const float rstd = rsqrtf(red[0] * (1.0f / (float)D_) + 1e-12f);

    const float* g  = gma + e * D_;
    const float* bb = bta + e * D_;
    float* hp = g_h1 + (long)t * D_;
    hp[tid]       = d0 * rstd * g[tid]       + bb[tid];
    hp[tid + 256] = d1 * rstd * g[tid + 256] + bb[tid + 256];
    hp[tid + 512] = d2 * rstd * g[tid + 512] + bb[tid + 512];
}

// ---------------------------------------------------------------------------
// out = LN(h1 + ffn) * g2[sel] + b2[sel]
// ---------------------------------------------------------------------------
__global__ __launch_bounds__(256)
void ln2_kernel(const float* __restrict__ gma, const float* __restrict__ bta,
                float* __restrict__ out)
{
    const int t = blockIdx.x;
    const int b = t >> 9;
    const int e = g_sel[b];
    const int tid = threadIdx.x;
    const float* hp = g_h1  + (long)t * D_;
    const float* fp = g_ffn + (long)t * D_;
    __shared__ float red[256];

    float v0 = hp[tid]       + fp[tid];
    float v1 = hp[tid + 256] + fp[tid + 256];
    float v2 = hp[tid + 512] + fp[tid + 512];

    red[tid] = v0 + v1 + v2; __syncthreads();
    for (int st = 128; st > 0; st >>= 1) { if (tid < st) red[tid] += red[tid + st]; __syncthreads(); }
    const float mean = red[0] * (1.0f / (float)D_);
    __syncthreads();
    float d0 = v0 - mean, d1 = v1 - mean, d2 = v2 - mean;
    red[tid] = d0*d0 + d1*d1 + d2*d2; __syncthreads();
    for (int st = 128; st > 0; st >>= 1) { if (tid < st) red[tid] += red[tid + st]; __syncthreads(); }
    const float rstd = rsqrtf(red[0] * (1.0f / (float)D_) + 1e-12f);

    const float* g  = gma + e * D_;
    const float* bb = bta + e * D_;
    float* op = out + (long)t * D_;
    op[tid]       = d0 * rstd * g[tid]       + bb[tid];
    op[tid + 256] = d1 * rstd * g[tid + 256] + bb[tid + 256];
    op[tid + 512] = d2 * rstd * g[tid + 512] + bb[tid + 512];
}

// ---------------------------------------------------------------------------
extern "C" void kernel_launch(void* const* d_in, const int* in_sizes, int n_in,
                              void* d_out, int out_size)
{
    const float* x       = (const float*)d_in[0];
    const int*   mask    = (const int*)  d_in[1];
    const float* Wqkv    = (const float*)d_in[2];
    const float* Wd      = (const float*)d_in[3];
    const float* bd      = (const float*)d_in[4];
    const float* ln1g    = (const float*)d_in[5];
    const float* ln1b    = (const float*)d_in[6];
    const float* W1      = (const float*)d_in[7];
    const float* b1      = (const float*)d_in[8];
    const float* W2      = (const float*)d_in[9];
    const float* b2      = (const float*)d_in[10];
    const float* ln2g    = (const float*)d_in[11];
    const float* ln2b    = (const float*)d_in[12];
    const float* centers = (const float*)d_in[13];
    float* out = (float*)d_out;

    float *qkvp, *ctxp, *attp, *h1p, *midp, *ffnp;
    int* selp;
    cudaGetSymbolAddress((void**)&qkvp, g_qkv);
    cudaGetSymbolAddress((void**)&ctxp, g_ctx);
    cudaGetSymbolAddress((void**)&attp, g_att);
    cudaGetSymbolAddress((void**)&h1p,  g_h1);
    cudaGetSymbolAddress((void**)&midp, g_mid);
    cudaGetSymbolAddress((void**)&ffnp, g_ffn);
    cudaGetSymbolAddress((void**)&selp, g_sel);

    const int M = B_ * S_;   // 4096

    // 1. QKV for all experts: (4096 x 768) x (2304 x 768)^T per e
    mma_gemm<false, false><<<dim3(QKVW / 128, M / 128, E_), 256>>>(
        x, Wqkv, nullptr, qkvp, M, QKVW, D_,
        0L, 0L, (long)QKVW * D_, 0L, (long)M * QKVW, nullptr);

    // 2. Attention for all (e,b,h)
    attn_kernel<<<dim3(S_ / 64, H_, E_ * B_), 128>>>(mask);

    // 3. routing: mean ctx -> feat (tiny GEMM) -> argmin
    mean_ctx_kernel<<<E_ * B_, 768>>>();
    featgemm_kernel<<<dim3(D_ / 128, E_), 256>>>(Wd, bd);
    route_kernel<<<B_, 256>>>(centers);

    // 4. attention.dense ONLY for selected expert: per b, (512 x 768) x Wd[sel]^T
    mma_gemm<false, true><<<dim3(D_ / 128, S_ / 128, B_), 256>>>(
        ctxp, Wd, bd, attp, S_, D_, D_,
        (long)S_ * D_, (long)B_ * S_ * D_, (long)D_ * D_, (long)D_,
        (long)S_ * D_, selp);

    // 5. post-attention LN (selected expert only)
    add_ln1_kernel<<<M, 256>>>(x, ln1g, ln1b);

    // 6. FFN (selected expert only): gelu(h1 @ W1^T + b1)
    mma_gemm<true, true><<<dim3(DFF_ / 128, S_ / 128, B_), 256>>>(
        h1p, W1, b1, midp, S_, DFF_, D_,
        (long)S_ * D_, 0L, (long)DFF_ * D_, (long)DFF_, (long)S_ * DFF_, selp);

    // 7. mid @ W2^T + b2
    mma_gemm<false, true><<<dim3(D_ / 128, S_ / 128, B_), 256>>>(
        midp, W2, b2, ffnp, S_, D_, DFF_,
        (long)S_ * DFF_, 0L, (long)D_ * DFF_, (long)D_, (long)S_ * D_, selp);

    // 8. final LN -> output
    ln2_kernel<<<M, 256>>>(ln2g, ln2b, out);
}

// round 12
// speedup vs baseline: 2.8057x; 1.8328x over previous
#include <cuda_runtime.h>
#include <math.h>

// Problem dims (fixed by the dataset)
#define E_   8
#define B_   8
#define S_   512
#define D_   768
#define H_   12
#define DH_  64
#define DFF_ 3072
#define QKVW 2304   // H_ * 3 * DH_

#define SCALE_F 0.036084391824351615f   // D_^-0.5

// ---------------------------------------------------------------------------
// Scratch: __device__ globals (no cudaMalloc allowed)
// ---------------------------------------------------------------------------
static __device__ float g_qkv [(size_t)E_ * B_ * S_ * QKVW];  // [e][b*S+s][h*192+k]
static __device__ float g_ctx [(size_t)E_ * B_ * S_ * D_];    // [e][t][h*64+d]
static __device__ float g_mctx[E_ * B_ * D_];                 // seq-mean of ctx
static __device__ float g_att [(size_t)B_ * S_ * D_];         // dense out, SELECTED expert
static __device__ float g_feat[E_ * B_ * D_];
static __device__ int   g_sel[B_];
static __device__ float g_h1 [(size_t)B_ * S_ * D_];
static __device__ float g_mid[(size_t)B_ * S_ * DFF_];
static __device__ float g_ffn[(size_t)B_ * S_ * D_];

// ---------------------------------------------------------------------------
// Helpers
// ---------------------------------------------------------------------------
__device__ __forceinline__ float f2tf32(float x) {
    unsigned u;
    asm("cvt.rna.tf32.f32 %0, %1;" : "=r"(u) : "f"(x));
    return __uint_as_float(u);
}

#define MMA_TF32(d, a0, a1, a2, a3, b0, b1)                                   \
    asm volatile("mma.sync.aligned.m16n8k8.row.col.f32.tf32.tf32.f32 "        \
                 "{%0,%1,%2,%3}, {%4,%5,%6,%7}, {%8,%9}, {%0,%1,%2,%3};"      \
                 : "+f"(d[0]), "+f"(d[1]), "+f"(d[2]), "+f"(d[3])             \
                 : "r"(a0), "r"(a1), "r"(a2), "r"(a3), "r"(b0), "r"(b1));

// ---------------------------------------------------------------------------
// Tensor-core GEMM: C = A * W^T (+bias)(+gelu), tf32 inputs / fp32 accum.
// Software-pipelined: next k-tile's global loads are issued before compute.
// Block tile 128x128x16, 256 threads (8 warps, each 64x32 = 4x4 m16n8 tiles).
// Smem: m-major, k-interleaved: phys(k) = (k&8) | ((k&3)<<1) | ((k>>2)&1)
// ---------------------------------------------------------------------------
template<bool GELU, bool HASBIAS>
__global__ __launch_bounds__(256)
void mma_gemm(const float* __restrict__ A, const float* __restrict__ W,
              const float* __restrict__ bias, float* __restrict__ C,
              int M, int N, int K,
              long Az, long Asel, long Wz, long biasz, long Cz,
              const int* __restrict__ sel)
{
    const int z = blockIdx.z;
    const int w = sel ? sel[z] : z;
    A += (long)z * Az + (sel ? (long)w * Asel : 0L);
    W += (long)w * Wz;
    if (HASBIAS) bias += (long)w * biasz;
    C += (long)z * Cz;

    __shared__ float As[128][20];   // [m][phys_k], 16 used + pad
    __shared__ float Bs[128][20];   // [n][phys_k]

    const int tid  = threadIdx.x;
    const int m0   = blockIdx.y * 128;
    const int n0   = blockIdx.x * 128;
    const int warp = tid >> 5;
    const int lane = tid & 31;
    const int wm   = (warp & 1) * 64;     // warp row offset
    const int wn   = (warp >> 1) * 32;    // warp col offset
    const int g    = lane >> 2;           // groupID   0..7
    const int kc   = lane & 3;            // tid-in-grp 0..3

    float acc[4][4][4];
    #pragma unroll
    for (int i = 0; i < 4; i++)
        #pragma unroll
        for (int j = 0; j < 4; j++)
            #pragma unroll
            for (int q = 0; q < 4; q++) acc[i][j][q] = 0.f;

    const int lc = (tid & 3) * 4;    // k offset of this thread's float4
    const int lr = tid >> 2;         // row 0..63 (+64 second iter)
    int pc[4];
    #pragma unroll
    for (int q = 0; q < 4; q++) {
        int k = lc + q;
        pc[q] = (k & 8) | ((k & 3) << 1) | ((k >> 2) & 1);
    }

    float4 va[2], vb[2];
    #pragma unroll
    for (int i = 0; i < 2; i++) {
        va[i] = *(const float4*)&A[(long)(m0 + lr + i * 64) * K + lc];
        vb[i] = *(const float4*)&W[(long)(n0 + lr + i * 64) * K + lc];
    }

    for (int k0 = 0; k0 < K; k0 += 16) {
        #pragma unroll
        for (int i = 0; i < 2; i++) {
            const int r = lr + i * 64;
            As[r][pc[0]] = f2tf32(va[i].x); As[r][pc[1]] = f2tf32(va[i].y);
            As[r][pc[2]] = f2tf32(va[i].z); As[r][pc[3]] = f2tf32(va[i].w);
            Bs[r][pc[0]] = f2tf32(vb[i].x); Bs[r][pc[1]] = f2tf32(vb[i].y);
            Bs[r][pc[2]] = f2tf32(vb[i].z); Bs[r][pc[3]] = f2tf32(vb[i].w);
        }
        __syncthreads();

        if (k0 + 16 < K) {   // prefetch next tile (overlaps with mma below)
            #pragma unroll
            for (int i = 0; i < 2; i++) {
                va[i] = *(const float4*)&A[(long)(m0 + lr + i * 64) * K + k0 + 16 + lc];
                vb[i] = *(const float4*)&W[(long)(n0 + lr + i * 64) * K + k0 + 16 + lc];
            }
        }

        #pragma unroll
        for (int ks = 0; ks < 2; ks++) {
            const int kb = ks * 8 + 2 * kc;
            unsigned af[4][4], bf[4][2];
            #pragma unroll
            for (int i = 0; i < 4; i++) {
                const int r = wm + i * 16 + g;
                float2 a02 = *(const float2*)&As[r][kb];
                float2 a13 = *(const float2*)&As[r + 8][kb];
                af[i][0] = __float_as_uint(a02.x);
                af[i][1] = __float_as_uint(a13.x);
                af[i][2] = __float_as_uint(a02.y);
                af[i][3] = __float_as_uint(a13.y);
            }
            #pragma unroll
            for (int j = 0; j < 4; j++) {
                const int c = wn + j * 8 + g;
                float2 b01 = *(const float2*)&Bs[c][kb];
                bf[j][0] = __float_as_uint(b01.x);
                bf[j][1] = __float_as_uint(b01.y);
            }
            #pragma unroll
            for (int i = 0; i < 4; i++)
                #pragma unroll
                for (int j = 0; j < 4; j++)
                    MMA_TF32(acc[i][j], af[i][0], af[i][1], af[i][2], af[i][3],
                             bf[j][0], bf[j][1]);
        }
        __syncthreads();
    }

    #pragma unroll
    for (int i = 0; i < 4; i++) {
        const long row0 = m0 + wm + i * 16 + g;
        #pragma unroll
        for (int j = 0; j < 4; j++) {
            const int col = n0 + wn + j * 8 + 2 * kc;
            float v0 = acc[i][j][0], v1 = acc[i][j][1];
            float v2 = acc[i][j][2], v3 = acc[i][j][3];
            if (HASBIAS) {
                float bb0 = bias[col], bb1 = bias[col + 1];
                v0 += bb0; v1 += bb1; v2 += bb0; v3 += bb1;
            }
            if (GELU) {
                v0 = 0.5f * v0 * (1.0f + erff(v0 * 0.7071067811865476f));
                v1 = 0.5f * v1 * (1.0f + erff(v1 * 0.7071067811865476f));
                v2 = 0.5f * v2 * (1.0f + erff(v2 * 0.7071067811865476f));
                v3 = 0.5f * v3 * (1.0f + erff(v3 * 0.7071067811865476f));
            }
            float2 lo = {v0, v1}, hi = {v2, v3};
            *(float2*)&C[row0 * N + col]       = lo;
            *(float2*)&C[(row0 + 8) * N + col] = hi;
        }
    }
}

// ---------------------------------------------------------------------------
// Tensor-core flash attention. Block = (qt 64 rows, h, eb). 128 threads,
// 4 warps x m16. Q frags in regs (pre-scaled tf32). K tile and P share one
// smem buffer (KP); V is stored transposed (Vt[dh][phys(key)]).
// Interleave: phys(k) within 8-chunk = ((k&3)<<1)|((k>>2)&1) so fragment
// pairs (k, k+4) are adjacent -> float2 loads.
// ---------------------------------------------------------------------------
#define AP 76   // smem pitch

__global__ __launch_bounds__(128)
void attn_mma_kernel(const int* __restrict__ mask)
{
    const int qt  = blockIdx.x;        // 0..7
    const int h   = blockIdx.y;        // 0..11
    const int eb  = blockIdx.z;        // e*8 + b
    const int b   = eb & 7;
    const int tid = threadIdx.x;
    const int warp = tid >> 5, lane = tid & 31;
    const int g = lane >> 2, kc = lane & 3;
    const int wm = warp * 16;

    const long rowbase = (long)eb * S_ * QKVW + h * 192;

    __shared__ float KP[64][AP];   // K tile, then P tile (lifetimes disjoint)
    __shared__ float Vt[64][AP];   // transposed V: [dh][phys(key)]
    __shared__ float sbias[64];

    const int lrow = tid >> 1;        // loader row 0..63
    const int lc0  = (tid & 1) * 32;  // loader column half

    // ---- stage Q (scaled + tf32) into KP, build A-fragments in registers
    {
        const float* qp = g_qkv + rowbase + (long)(qt * 64 + lrow) * QKVW + lc0;
        #pragma unroll
        for (int i = 0; i < 8; i++) {
            float4 v = *(const float4*)(qp + 4 * i);
            const int d  = lc0 + 4 * i;
            const int pb = (d & ~7) | ((d >> 2) & 1);
            KP[lrow][pb + 0] = f2tf32(v.x * SCALE_F);
            KP[lrow][pb + 2] = f2tf32(v.y * SCALE_F);
            KP[lrow][pb + 4] = f2tf32(v.z * SCALE_F);
            KP[lrow][pb + 6] = f2tf32(v.w * SCALE_F);
        }
    }
    __syncthreads();

    unsigned qf[8][4];
    #pragma unroll
    for (int ks = 0; ks < 8; ks++) {
        float2 lo = *(const float2*)&KP[wm + g][ks * 8 + 2 * kc];
        float2 hi = *(const float2*)&KP[wm + g + 8][ks * 8 + 2 * kc];
        qf[ks][0] = __float_as_uint(lo.x);
        qf[ks][1] = __float_as_uint(hi.x);
        qf[ks][2] = __float_as_uint(lo.y);
        qf[ks][3] = __float_as_uint(hi.y);
    }

    float oacc[8][4];
    #pragma unroll
    for (int nt = 0; nt < 8; nt++)
        #pragma unroll
        for (int q = 0; q < 4; q++) oacc[nt][q] = 0.f;
    float m0 = -1e30f, m1 = -1e30f, l0 = 0.f, l1 = 0.f;

    const int c2k   = 2 * kc;
    const int pcol0 = ((c2k & 3) << 1) | ((c2k >> 2) & 1);           // phys(2kc)
    const int pcol1 = (((c2k + 1) & 3) << 1) | (((c2k + 1) >> 2) & 1); // phys(2kc+1)
    const int pkey  = (lrow & ~7) | ((lrow & 3) << 1) | ((lrow >> 2) & 1);

    for (int kt = 0; kt < 8; kt++) {
        __syncthreads();   // previous users of KP / Vt are done
        // ---- load K (interleaved), V (transposed), mask bias
        {
            const float* kp = g_qkv + rowbase + (long)(kt * 64 + lrow) * QKVW + 64 + lc0;
            const float* vp = kp + 64;
            #pragma unroll
            for (int i = 0; i < 8; i++) {
                float4 kv = *(const float4*)(kp + 4 * i);
                const int d  = lc0 + 4 * i;
                const int pb = (d & ~7) | ((d >> 2) & 1);
                KP[lrow][pb + 0] = f2tf32(kv.x);
                KP[lrow][pb + 2] = f2tf32(kv.y);
                KP[lrow][pb + 4] = f2tf32(kv.z);
                KP[lrow][pb + 6] = f2tf32(kv.w);
                float4 vv = *(const float4*)(vp + 4 * i);
                Vt[d + 0][pkey] = f2tf32(vv.x);
                Vt[d + 1][pkey] = f2tf32(vv.y);
                Vt[d + 2][pkey] = f2tf32(vv.z);
                Vt[d + 3][pkey] = f2tf32(vv.w);
            }
            if (tid < 64)
                sbias[tid] = (mask[b * S_ + kt * 64 + tid] == 0) ? -1e30f : 0.f;
        }
        __syncthreads();

        // ---- scores S = Q @ K^T  (C cols = key = nt*8 + 2kc + {0,1})
        float sacc[8][4];
        #pragma unroll
        for (int nt = 0; nt < 8; nt++) {
            #pragma unroll
            for (int q = 0; q < 4; q++) sacc[nt][q] = 0.f;
            #pragma unroll
            for (int ks = 0; ks < 8; ks++) {
                float2 bb = *(const float2*)&KP[nt * 8 + g][ks * 8 + 2 * kc];
                MMA_TF32(sacc[nt], qf[ks][0], qf[ks][1], qf[ks][2], qf[ks][3],
                         __float_as_uint(bb.x), __float_as_uint(bb.y));
            }
        }

        // ---- mask + online softmax (rows g and g+8 of this warp's m16)
        float mx0 = -1e30f, mx1 = -1e30f;
        #pragma unroll
        for (int nt = 0; nt < 8; nt++) {
            float b0 = sbias[nt * 8 + c2k], b1 = sbias[nt * 8 + c2k + 1];
            sacc[nt][0] += b0; sacc[nt][1] += b1;
            sacc[nt][2] += b0; sacc[nt][3] += b1;
            mx0 = fmaxf(mx0, fmaxf(sacc[nt][0], sacc[nt][1]));
            mx1 = fmaxf(mx1, fmaxf(sacc[nt][2], sacc[nt][3]));
        }
        mx0 = fmaxf(mx0, __shfl_xor_sync(0xffffffffu, mx0, 1));
        mx0 = fmaxf(mx0, __shfl_xor_sync(0xffffffffu, mx0, 2));
        mx1 = fmaxf(mx1, __shfl_xor_sync(0xffffffffu, mx1, 1));
        mx1 = fmaxf(mx1, __shfl_xor_sync(0xffffffffu, mx1, 2));
        const float mn0 = fmaxf(m0, mx0), mn1 = fmaxf(m1, mx1);
        const float cr0 = __expf(m0 - mn0), cr1 = __expf(m1 - mn1);
        m0 = mn0; m1 = mn1;

        float ll0 = 0.f, ll1 = 0.f;
        #pragma unroll
        for (int nt = 0; nt < 8; nt++) {
            sacc[nt][0] = __expf(sacc[nt][0] - mn0);
            sacc[nt][1] = __expf(sacc[nt][1] - mn0);
            sacc[nt][2] = __expf(sacc[nt][2] - mn1);
            sacc[nt][3] = __expf(sacc[nt][3] - mn1);
            ll0 += sacc[nt][0] + sacc[nt][1];
            ll1 += sacc[nt][2] + sacc[nt][3];
        }
        ll0 += __shfl_xor_sync(0xffffffffu, ll0, 1);
        ll0 += __shfl_xor_sync(0xffffffffu, ll0, 2);
        ll1 += __shfl_xor_sync(0xffffffffu, ll1, 1);
        ll1 += __shfl_xor_sync(0xffffffffu, ll1, 2);
        l0 = l0 * cr0 + ll0;
        l1 = l1 * cr1 + ll1;
        #pragma unroll
        for (int nt = 0; nt < 8; nt++) {
            oacc[nt][0] *= cr0; oacc[nt][1] *= cr0;
            oacc[nt][2] *= cr1; oacc[nt][3] *= cr1;
        }

        __syncthreads();   // all warps finished reading K from KP
        // ---- store P (tf32, interleaved) into KP (own warp's 16 rows)
        #pragma unroll
        for (int nt = 0; nt < 8; nt++) {
            KP[wm + g][nt * 8 + pcol0]     = f2tf32(sacc[nt][0]);
            KP[wm + g][nt * 8 + pcol1]     = f2tf32(sacc[nt][1]);
            KP[wm + g + 8][nt * 8 + pcol0] = f2tf32(sacc[nt][2]);
            KP[wm + g + 8][nt * 8 + pcol1] = f2tf32(sacc[nt][3]);
        }
        __syncwarp();

        // ---- O += P @ V   (A = P rows of this warp, B = Vt)
        #pragma unroll
        for (int ks2 = 0; ks2 < 8; ks2++) {
            float2 lo = *(const float2*)&KP[wm + g][ks2 * 8 + 2 * kc];
            float2 hi = *(const float2*)&KP[wm + g + 8][ks2 * 8 + 2 * kc];
            const unsigned a0 = __float_as_uint(lo.x), a1 = __float_as_uint(hi.x);
            const unsigned a2 = __float_as_uint(lo.y), a3 = __float_as_uint(hi.y);
            #pragma unroll
            for (int nt = 0; nt < 8; nt++) {
                float2 vb = *(const float2*)&Vt[nt * 8 + g][ks2 * 8 + 2 * kc];
                MMA_TF32(oacc[nt], a0, a1, a2, a3,
                         __float_as_uint(vb.x), __float_as_uint(vb.y));
            }
        }
    }

    // ---- epilogue
    const float inv0 = 1.f / l0, inv1 = 1.f / l1;
    float* op0 = g_ctx + ((long)eb * S_ + qt * 64 + wm + g) * D_ + h * 64;
    float* op1 = op0 + 8L * D_;
    #pragma unroll
    for (int nt = 0; nt < 8; nt++) {
        float2 v0 = {oacc[nt][0] * inv0, oacc[nt][1] * inv0};
        float2 v1 = {oacc[nt][2] * inv1, oacc[nt][3] * inv1};
        *(float2*)(op0 + nt * 8 + c2k) = v0;
        *(float2*)(op1 + nt * 8 + c2k) = v1;
    }
}

// ---------------------------------------------------------------------------
// mctx[eb,:] = mean over S of g_ctx[eb,:,:]
// ---------------------------------------------------------------------------
__global__ __launch_bounds__(768)
void mean_ctx_kernel()
{
    const int eb = blockIdx.x;
    const int d  = threadIdx.x;
    const float* p = g_ctx + (long)eb * S_ * D_ + d;
    float s = 0.f;
    #pragma unroll 8
    for (int t = 0; t < S_; t++) s += p[(long)t * D_];
    g_mctx[eb * D_ + d] = s * (1.0f / (float)S_);
}

// ---------------------------------------------------------------------------
// feat[e,b,n] = mctx[e,b,:] . Wd[e,n,:] + bd[e,n]   (exactly mean_s(att))
// ---------------------------------------------------------------------------
__global__ __launch_bounds__(256)
void featgemm_kernel(const float* __restrict__ Wd, const float* __restrict__ bd)
{
    const int e  = blockIdx.y;
    const int nc = blockIdx.x;
    const int tid = threadIdx.x, warp = tid >> 5, lane = tid & 31;

    __shared__ float mc[8][768];
    for (int i = tid; i < 8 * 768; i += 256)
        mc[i / 768][i % 768] = g_mctx[(e * 8 + i / 768) * D_ + i % 768];
    __syncthreads();

    for (int rr = 0; rr < 16; rr++) {
        const int n = nc * 128 + warp * 16 + rr;
        const float* wp = Wd + ((long)e * D_ + n) * D_;
        float wreg[24];
        #pragma unroll
        for (int j = 0; j < 24; j++) wreg[j] = wp[lane + 32 * j];
        #pragma unroll
        for (int b = 0; b < 8; b++) {
            float s = 0.f;
            #pragma unroll
            for (int j = 0; j < 24; j++) s += wreg[j] * mc[b][lane + 32 * j];
            #pragma unroll
            for (int off = 16; off > 0; off >>= 1)
                s += __shfl_xor_sync(0xffffffffu, s, off);
            if (lane == 0)
                g_feat[(e * 8 + b) * D_ + n] = s + bd[e * D_ + n];
        }
    }
}

// ---------------------------------------------------------------------------
// sel[b] = argmin_e ||feat[e,b] - centers[e]||
// ---------------------------------------------------------------------------
__global__ __launch_bounds__(256)
void route_kernel(const float* __restrict__ centers)
{
    const int b = blockIdx.x, tid = threadIdx.x;
    __shared__ float red[256];
    float best = 3.4e38f;
    int   bi   = 0;
    for (int e = 0; e < E_; e++) {
        float s = 0.f;
        const float* fp = g_feat + (e * B_ + b) * D_;
        const float* cp = centers + e * D_;
        for (int d = tid; d < D_; d += 256) {
            float df = fp[d] - cp[d];
            s += df * df;
        }
        red[tid] = s; __syncthreads();
        for (int st = 128; st > 0; st >>= 1) {
            if (tid < st) red[tid] += red[tid + st];
            __syncthreads();
        }
        if (tid == 0 && red[0] < best) { best = red[0]; bi = e; }
        __syncthreads();
    }
    if (tid == 0) g_sel[b] = bi;
}

// ---------------------------------------------------------------------------
// h1 = LN(att_sel + x) * g1[sel] + b1[sel]
// ---------------------------------------------------------------------------
__global__ __launch_bounds__(256)
void add_ln1_kernel(const float* __restrict__ x,
                    const float* __restrict__ gma, const float* __restrict__ bta)
{
    const int t = blockIdx.x;           // b*512 + s
    const int b = t >> 9;
    const int e = g_sel[b];
    const int tid = threadIdx.x;
    const float* ap = g_att + (long)t * D_;
    const float* xp = x + (long)t * D_;
    __shared__ float red[256];

    float v0 = ap[tid]       + xp[tid];
    float v1 = ap[tid + 256] + xp[tid + 256];
    float v2 = ap[tid + 512] + xp[tid + 512];

    red[tid] = v0 + v1 + v2; __syncthreads();
    for (int st = 128; st > 0; st >>= 1) { if (tid < st) red[tid] += red[tid + st]; __syncthreads(); }
    const float mean = red[0] * (1.0f / (float)D_);
    __syncthreads();
    float d0 = v0 - mean, d1 = v1 - mean, d2 = v2 - mean;
    red[tid] = d0*d0 + d1*d1 + d2*d2; __syncthreads();
    for (int st = 128; st > 0; st >>= 1) { if (tid < st) red[tid] += red[tid + st]; __syncthreads(); }
    const float rstd = rsqrtf(red[0] * (1.0f / (float)D_) + 1e-12f);

    const float* g  = gma + e * D_;
    const float* bb = bta + e * D_;
    float* hp = g_h1 + (long)t * D_;
    hp[tid]       = d0 * rstd * g[tid]       + bb[tid];
    hp[tid + 256] = d1 * rstd * g[tid + 256] + bb[tid + 256];
    hp[tid + 512] = d2 * rstd * g[tid + 512] + bb[tid + 512];
}

// ---------------------------------------------------------------------------
// out = LN(h1 + ffn) * g2[sel] + b2[sel]
// ---------------------------------------------------------------------------
__global__ __launch_bounds__(256)
void ln2_kernel(const float* __restrict__ gma, const float* __restrict__ bta,
                float* __restrict__ out)
{
    const int t = blockIdx.x;
    const int b = t >> 9;
    const int e = g_sel[b];
    const int tid = threadIdx.x;
    const float* hp = g_h1  + (long)t * D_;
    const float* fp = g_ffn + (long)t * D_;
    __shared__ float red[256];

    float v0 = hp[tid]       + fp[tid];
    float v1 = hp[tid + 256] + fp[tid + 256];
    float v2 = hp[tid + 512] + fp[tid + 512];

    red[tid] = v0 + v1 + v2; __syncthreads();
    for (int st = 128; st > 0; st >>= 1) { if (tid < st) red[tid] += red[tid + st]; __syncthreads(); }
    const float mean = red[0] * (1.0f / (float)D_);
    __syncthreads();
    float d0 = v0 - mean, d1 = v1 - mean, d2 = v2 - mean;
    red[tid] = d0*d0 + d1*d1 + d2*d2; __syncthreads();
    for (int st = 128; st > 0; st >>= 1) { if (tid < st) red[tid] += red[tid + st]; __syncthreads(); }
    const float rstd = rsqrtf(red[0] * (1.0f / (float)D_) + 1e-12f);

    const float* g  = gma + e * D_;
    const float* bb = bta + e * D_;
    float* op = out + (long)t * D_;
    op[tid]       = d0 * rstd * g[tid]       + bb[tid];
    op[tid + 256] = d1 * rstd * g[tid + 256] + bb[tid + 256];
    op[tid + 512] = d2 * rstd * g[tid + 512] + bb[tid + 512];
}

// ---------------------------------------------------------------------------
extern "C" void kernel_launch(void* const* d_in, const int* in_sizes, int n_in,
                              void* d_out, int out_size)
{
    const float* x       = (const float*)d_in[0];
    const int*   mask    = (const int*)  d_in[1];
    const float* Wqkv    = (const float*)d_in[2];
    const float* Wd      = (const float*)d_in[3];
    const float* bd      = (const float*)d_in[4];
    const float* ln1g    = (const float*)d_in[5];
    const float* ln1b    = (const float*)d_in[6];
    const float* W1      = (const float*)d_in[7];
    const float* b1      = (const float*)d_in[8];
    const float* W2      = (const float*)d_in[9];
    const float* b2      = (const float*)d_in[10];
    const float* ln2g    = (const float*)d_in[11];
    const float* ln2b    = (const float*)d_in[12];
    const float* centers = (const float*)d_in[13];
    float* out = (float*)d_out;

    float *qkvp, *ctxp, *attp, *h1p, *midp, *ffnp;
    int* selp;
    cudaGetSymbolAddress((void**)&qkvp, g_qkv);
    cudaGetSymbolAddress((void**)&ctxp, g_ctx);
    cudaGetSymbolAddress((void**)&attp, g_att);
    cudaGetSymbolAddress((void**)&h1p,  g_h1);
    cudaGetSymbolAddress((void**)&midp, g_mid);
    cudaGetSymbolAddress((void**)&ffnp, g_ffn);
    cudaGetSymbolAddress((void**)&selp, g_sel);

    const int M = B_ * S_;   // 4096

    // 1. QKV for all experts: (4096 x 768) x (2304 x 768)^T per e
    mma_gemm<false, false><<<dim3(QKVW / 128, M / 128, E_), 256>>>(
        x, Wqkv, nullptr, qkvp, M, QKVW, D_,
        0L, 0L, (long)QKVW * D_, 0L, (long)M * QKVW, nullptr);

    // 2. Attention for all (e,b,h) on tensor cores
    attn_mma_kernel<<<dim3(S_ / 64, H_, E_ * B_), 128>>>(mask);

    // 3. routing: mean ctx -> feat (tiny GEMM) -> argmin
    mean_ctx_kernel<<<E_ * B_, 768>>>();
    featgemm_kernel<<<dim3(D_ / 128, E_), 256>>>(Wd, bd);
    route_kernel<<<B_, 256>>>(centers);

    // 4. attention.dense ONLY for selected expert: per b, (512 x 768) x Wd[sel]^T
    mma_gemm<false, true><<<dim3(D_ / 128, S_ / 128, B_), 256>>>(
        ctxp, Wd, bd, attp, S_, D_, D_,
        (long)S_ * D_, (long)B_ * S_ * D_, (long)D_ * D_, (long)D_,
        (long)S_ * D_, selp);

    // 5. post-attention LN (selected expert only)
    add_ln1_kernel<<<M, 256>>>(x, ln1g, ln1b);

    // 6. FFN (selected expert only): gelu(h1 @ W1^T + b1)
    mma_gemm<true, true><<<dim3(DFF_ / 128, S_ / 128, B_), 256>>>(
        h1p, W1, b1, midp, S_, DFF_, D_,
        (long)S_ * D_, 0L, (long)DFF_ * D_, (long)DFF_, (long)S_ * DFF_, selp);

    // 7. mid @ W2^T + b2
    mma_gemm<false, true><<<dim3(D_ / 128, S_ / 128, B_), 256>>>(
        midp, W2, b2, ffnp, S_, D_, DFF_,
        (long)S_ * DFF_, 0L, (long)D_ * DFF_, (long)D_, (long)S_ * D_, selp);

    // 8. final LN -> output
    ln2_kernel<<<M, 256>>>(ln2g, ln2b, out);
}

// round 14
// speedup vs baseline: 2.8555x; 1.0178x over previous
#include <cuda_runtime.h>
#include <math.h>

// Problem dims (fixed by the dataset)
#define E_   8
#define B_   8
#define S_   512
#define D_   768
#define H_   12
#define DH_  64
#define DFF_ 3072
#define QKVW 2304   // H_ * 3 * DH_

#define SCALE_F 0.036084391824351615f   // D_^-0.5

// ---------------------------------------------------------------------------
// Scratch: __device__ globals (no cudaMalloc allowed)
// ---------------------------------------------------------------------------
static __device__ float g_qkv [(size_t)E_ * B_ * S_ * QKVW];  // [e][b*S+s][h*192+k]
static __device__ float g_ctx [(size_t)E_ * B_ * S_ * D_];    // [e][t][h*64+d]
static __device__ float g_mpart[(size_t)E_ * B_ * 8 * D_];    // partial seq-sums of ctx
static __device__ float g_att [(size_t)B_ * S_ * D_];         // dense out, SELECTED expert
static __device__ float g_feat[E_ * B_ * D_];
static __device__ int   g_sel[B_];
static __device__ float g_h1 [(size_t)B_ * S_ * D_];
static __device__ float g_mid[(size_t)B_ * S_ * DFF_];
static __device__ float g_ffn[(size_t)B_ * S_ * D_];

// ---------------------------------------------------------------------------
// mma.tf32 consumes raw fp32 register bits (HW truncates the low mantissa
// bits), so no explicit cvt.rna.tf32 is needed on operand staging.
// ---------------------------------------------------------------------------
#define MMA_TF32(d, a0, a1, a2, a3, b0, b1)                                   \
    asm volatile("mma.sync.aligned.m16n8k8.row.col.f32.tf32.tf32.f32 "        \
                 "{%0,%1,%2,%3}, {%4,%5,%6,%7}, {%8,%9}, {%0,%1,%2,%3};"      \
                 : "+f"(d[0]), "+f"(d[1]), "+f"(d[2]), "+f"(d[3])             \
                 : "r"(a0), "r"(a1), "r"(a2), "r"(a3), "r"(b0), "r"(b1));

// ---------------------------------------------------------------------------
// Tensor-core GEMM: C = A * W^T (+bias)(+gelu), tf32 mma / fp32 accum.
// 2-stage smem double buffer, register prefetch, ONE __syncthreads per iter.
// Block tile 128x128x16, 256 threads (8 warps, each 64x32 = 4x4 m16n8 tiles).
// Smem: m-major, k-interleaved: phys(k) = (k&8) | ((k&3)<<1) | ((k>>2)&1)
// so fragment pairs (k, k+4) are adjacent -> LDS.64.
// ---------------------------------------------------------------------------
template<bool GELU, bool HASBIAS>
__global__ __launch_bounds__(256)
void mma_gemm(const float* __restrict__ A, const float* __restrict__ W,
              const float* __restrict__ bias, float* __restrict__ C,
              int M, int N, int K,
              long Az, long Asel, long Wz, long biasz, long Cz,
              const int* __restrict__ sel)
{
    const int z = blockIdx.z;
    const int w = sel ? sel[z] : z;
    A += (long)z * Az + (sel ? (long)w * Asel : 0L);
    W += (long)w * Wz;
    if (HASBIAS) bias += (long)w * biasz;
    C += (long)z * Cz;

    __shared__ float As[2][128][20];   // [stage][m][phys_k]
    __shared__ float Bs[2][128][20];   // [stage][n][phys_k]

    const int tid  = threadIdx.x;
    const int m0   = blockIdx.y * 128;
    const int n0   = blockIdx.x * 128;
    const int warp = tid >> 5;
    const int lane = tid & 31;
    const int wm   = (warp & 1) * 64;     // warp row offset
    const int wn   = (warp >> 1) * 32;    // warp col offset
    const int g    = lane >> 2;           // groupID   0..7
    const int kc   = lane & 3;            // tid-in-grp 0..3

    float acc[4][4][4];
    #pragma unroll
    for (int i = 0; i < 4; i++)
        #pragma unroll
        for (int j = 0; j < 4; j++)
            #pragma unroll
            for (int q = 0; q < 4; q++) acc[i][j][q] = 0.f;

    const int lc = (tid & 3) * 4;    // k offset of this thread's float4
    const int lr = tid >> 2;         // row 0..63 (+64 second iter)
    int pc[4];
    #pragma unroll
    for (int q = 0; q < 4; q++) {
        int k = lc + q;
        pc[q] = (k & 8) | ((k & 3) << 1) | ((k >> 2) & 1);
    }

    float4 va[2], vb[2];
    #pragma unroll
    for (int i = 0; i < 2; i++) {
        va[i] = *(const float4*)&A[(long)(m0 + lr + i * 64) * K + lc];
        vb[i] = *(const float4*)&W[(long)(n0 + lr + i * 64) * K + lc];
    }
    #pragma unroll
    for (int i = 0; i < 2; i++) {
        const int r = lr + i * 64;
        As[0][r][pc[0]] = va[i].x; As[0][r][pc[1]] = va[i].y;
        As[0][r][pc[2]] = va[i].z; As[0][r][pc[3]] = va[i].w;
        Bs[0][r][pc[0]] = vb[i].x; Bs[0][r][pc[1]] = vb[i].y;
        Bs[0][r][pc[2]] = vb[i].z; Bs[0][r][pc[3]] = vb[i].w;
    }
    __syncthreads();

    for (int k0 = 0; k0 < K; k0 += 16) {
        const int st   = (k0 >> 4) & 1;
        const bool more = (k0 + 16 < K);

        if (more) {   // prefetch next tile into registers (overlaps mma)
            #pragma unroll
            for (int i = 0; i < 2; i++) {
                va[i] = *(const float4*)&A[(long)(m0 + lr + i * 64) * K + k0 + 16 + lc];
                vb[i] = *(const float4*)&W[(long)(n0 + lr + i * 64) * K + k0 + 16 + lc];
            }
        }

        #pragma unroll
        for (int ks = 0; ks < 2; ks++) {
            const int kb = ks * 8 + 2 * kc;
            unsigned af[4][4], bf[4][2];
            #pragma unroll
            for (int i = 0; i < 4; i++) {
                const int r = wm + i * 16 + g;
                float2 a02 = *(const float2*)&As[st][r][kb];
                float2 a13 = *(const float2*)&As[st][r + 8][kb];
                af[i][0] = __float_as_uint(a02.x);
                af[i][1] = __float_as_uint(a13.x);
                af[i][2] = __float_as_uint(a02.y);
                af[i][3] = __float_as_uint(a13.y);
            }
            #pragma unroll
            for (int j = 0; j < 4; j++) {
                const int c = wn + j * 8 + g;
                float2 b01 = *(const float2*)&Bs[st][c][kb];
                bf[j][0] = __float_as_uint(b01.x);
                bf[j][1] = __float_as_uint(b01.y);
            }
            #pragma unroll
            for (int i = 0; i < 4; i++)
                #pragma unroll
                for (int j = 0; j < 4; j++)
                    MMA_TF32(acc[i][j], af[i][0], af[i][1], af[i][2], af[i][3],
                             bf[j][0], bf[j][1]);
        }

        if (more) {   // store prefetched tile into the other stage
            const int so = st ^ 1;
            #pragma unroll
            for (int i = 0; i < 2; i++) {
                const int r = lr + i * 64;
                As[so][r][pc[0]] = va[i].x; As[so][r][pc[1]] = va[i].y;
                As[so][r][pc[2]] = va[i].z; As[so][r][pc[3]] = va[i].w;
                Bs[so][r][pc[0]] = vb[i].x; Bs[so][r][pc[1]] = vb[i].y;
                Bs[so][r][pc[2]] = vb[i].z; Bs[so][r][pc[3]] = vb[i].w;
            }
        }
        __syncthreads();
    }

    #pragma unroll
    for (int i = 0; i < 4; i++) {
        const long row0 = m0 + wm + i * 16 + g;
        #pragma unroll
        for (int j = 0; j < 4; j++) {
            const int col = n0 + wn + j * 8 + 2 * kc;
            float v0 = acc[i][j][0], v1 = acc[i][j][1];
            float v2 = acc[i][j][2], v3 = acc[i][j][3];
            if (HASBIAS) {
                float bb0 = bias[col], bb1 = bias[col + 1];
                v0 += bb0; v1 += bb1; v2 += bb0; v3 += bb1;
            }
            if (GELU) {
                v0 = 0.5f * v0 * (1.0f + erff(v0 * 0.7071067811865476f));
                v1 = 0.5f * v1 * (1.0f + erff(v1 * 0.7071067811865476f));
                v2 = 0.5f * v2 * (1.0f + erff(v2 * 0.7071067811865476f));
                v3 = 0.5f * v3 * (1.0f + erff(v3 * 0.7071067811865476f));
            }
            float2 lo = {v0, v1}, hi = {v2, v3};
            *(float2*)&C[row0 * N + col]       = lo;
            *(float2*)&C[(row0 + 8) * N + col] = hi;
        }
    }
}

// ---------------------------------------------------------------------------
// Tensor-core flash attention. Block = (qt 64 rows, h, eb). 128 threads,
// 4 warps x m16. Raw fp32 bits feed the tf32 mma (HW truncates).
// ---------------------------------------------------------------------------
#define AP 76   // smem pitch

__global__ __launch_bounds__(128)
void attn_mma_kernel(const int* __restrict__ mask)
{
    const int qt  = blockIdx.x;        // 0..7
    const int h   = blockIdx.y;        // 0..11
    const int eb  = blockIdx.z;        // e*8 + b
    const int b   = eb & 7;
    const int tid = threadIdx.x;
    const int warp = tid >> 5, lane = tid & 31;
    const int g = lane >> 2, kc = lane & 3;
    const int wm = warp * 16;

    const long rowbase = (long)eb * S_ * QKVW + h * 192;

    __shared__ float KP[64][AP];   // K tile, then P tile (lifetimes disjoint)
    __shared__ float Vt[64][AP];   // transposed V: [dh][phys(key)]
    __shared__ float sbias[64];

    const int lrow = tid >> 1;        // loader row 0..63
    const int lc0  = (tid & 1) * 32;  // loader column half

    // ---- stage Q (scaled) into KP, build A-fragments in registers
    {
        const float* qp = g_qkv + rowbase + (long)(qt * 64 + lrow) * QKVW + lc0;
        #pragma unroll
        for (int i = 0; i < 8; i++) {
            float4 v = *(const float4*)(qp + 4 * i);
            const int d  = lc0 + 4 * i;
            const int pb = (d & ~7) | ((d >> 2) & 1);
            KP[lrow][pb + 0] = v.x * SCALE_F;
            KP[lrow][pb + 2] = v.y * SCALE_F;
            KP[lrow][pb + 4] = v.z * SCALE_F;
            KP[lrow][pb + 6] = v.w * SCALE_F;
        }
    }
    __syncthreads();

    unsigned qf[8][4];
    #pragma unroll
    for (int ks = 0; ks < 8; ks++) {
        float2 lo = *(const float2*)&KP[wm + g][ks * 8 + 2 * kc];
        float2 hi = *(const float2*)&KP[wm + g + 8][ks * 8 + 2 * kc];
        qf[ks][0] = __float_as_uint(lo.x);
        qf[ks][1] = __float_as_uint(hi.x);
        qf[ks][2] = __float_as_uint(lo.y);
        qf[ks][3] = __float_as_uint(hi.y);
    }

    float oacc[8][4];
    #pragma unroll
    for (int nt = 0; nt < 8; nt++)
        #pragma unroll
        for (int q = 0; q < 4; q++) oacc[nt][q] = 0.f;
    float m0 = -1e30f, m1 = -1e30f, l0 = 0.f, l1 = 0.f;

    const int c2k   = 2 * kc;
    const int pcol0 = ((c2k & 3) << 1) | ((c2k >> 2) & 1);
    const int pcol1 = (((c2k + 1) & 3) << 1) | (((c2k + 1) >> 2) & 1);
    const int pkey  = (lrow & ~7) | ((lrow & 3) << 1) | ((lrow >> 2) & 1);

    for (int kt = 0; kt < 8; kt++) {
        __syncthreads();   // previous users of KP / Vt are done
        {
            const float* kp = g_qkv + rowbase + (long)(kt * 64 + lrow) * QKVW + 64 + lc0;
            const float* vp = kp + 64;
            #pragma unroll
            for (int i = 0; i < 8; i++) {
                float4 kv = *(const float4*)(kp + 4 * i);
                const int d  = lc0 + 4 * i;
                const int pb = (d & ~7) | ((d >> 2) & 1);
                KP[lrow][pb + 0] = kv.x;
                KP[lrow][pb + 2] = kv.y;
                KP[lrow][pb + 4] = kv.z;
                KP[lrow][pb + 6] = kv.w;
                float4 vv = *(const float4*)(vp + 4 * i);
                Vt[d + 0][pkey] = vv.x;
                Vt[d + 1][pkey] = vv.y;
                Vt[d + 2][pkey] = vv.z;
                Vt[d + 3][pkey] = vv.w;
            }
            if (tid < 64)
                sbias[tid] = (mask[b * S_ + kt * 64 + tid] == 0) ? -1e30f : 0.f;
        }
        __syncthreads();

        // ---- scores S = Q @ K^T
        float sacc[8][4];
        #pragma unroll
        for (int nt = 0; nt < 8; nt++) {
            #pragma unroll
            for (int q = 0; q < 4; q++) sacc[nt][q] = 0.f;
            #pragma unroll
            for (int ks = 0; ks < 8; ks++) {
                float2 bb = *(const float2*)&KP[nt * 8 + g][ks * 8 + 2 * kc];
                MMA_TF32(sacc[nt], qf[ks][0], qf[ks][1], qf[ks][2], qf[ks][3],
                         __float_as_uint(bb.x), __float_as_uint(bb.y));
            }
        }

        // ---- mask + online softmax
        float mx0 = -1e30f, mx1 = -1e30f;
        #pragma unroll
        for (int nt = 0; nt < 8; nt++) {
            float b0 = sbias[nt * 8 + c2k], b1 = sbias[nt * 8 + c2k + 1];
            sacc[nt][0] += b0; sacc[nt][1] += b1;
            sacc[nt][2] += b0; sacc[nt][3] += b1;
            mx0 = fmaxf(mx0, fmaxf(sacc[nt][0], sacc[nt][1]));
            mx1 = fmaxf(mx1, fmaxf(sacc[nt][2], sacc[nt][3]));
        }
        mx0 = fmaxf(mx0, __shfl_xor_sync(0xffffffffu, mx0, 1));
        mx0 = fmaxf(mx0, __shfl_xor_sync(0xffffffffu, mx0, 2));
        mx1 = fmaxf(mx1, __shfl_xor_sync(0xffffffffu, mx1, 1));
        mx1 = fmaxf(mx1, __shfl_xor_sync(0xffffffffu, mx1, 2));
        const float mn0 = fmaxf(m0, mx0), mn1 = fmaxf(m1, mx1);
        const float cr0 = __expf(m0 - mn0), cr1 = __expf(m1 - mn1);
        m0 = mn0; m1 = mn1;

        float ll0 = 0.f, ll1 = 0.f;
        #pragma unroll
        for (int nt = 0; nt < 8; nt++) {
            sacc[nt][0] = __expf(sacc[nt][0] - mn0);
            sacc[nt][1] = __expf(sacc[nt][1] - mn0);
            sacc[nt][2] = __expf(sacc[nt][2] - mn1);
            sacc[nt][3] = __expf(sacc[nt][3] - mn1);
            ll0 += sacc[nt][0] + sacc[nt][1];
            ll1 += sacc[nt][2] + sacc[nt][3];
        }
        ll0 += __shfl_xor_sync(0xffffffffu, ll0, 1);
        ll0 += __shfl_xor_sync(0xffffffffu, ll0, 2);
        ll1 += __shfl_xor_sync(0xffffffffu, ll1, 1);
        ll1 += __shfl_xor_sync(0xffffffffu, ll1, 2);
        l0 = l0 * cr0 + ll0;
        l1 = l1 * cr1 + ll1;
        #pragma unroll
        for (int nt = 0; nt < 8; nt++) {
            oacc[nt][0] *= cr0; oacc[nt][1] *= cr0;
            oacc[nt][2] *= cr1; oacc[nt][3] *= cr1;
        }

        __syncthreads();   // all warps finished reading K from KP
        #pragma unroll
        for (int nt = 0; nt < 8; nt++) {
            KP[wm + g][nt * 8 + pcol0]     = sacc[nt][0];
            KP[wm + g][nt * 8 + pcol1]     = sacc[nt][1];
            KP[wm + g + 8][nt * 8 + pcol0] = sacc[nt][2];
            KP[wm + g + 8][nt * 8 + pcol1] = sacc[nt][3];
        }
        __syncwarp();

        // ---- O += P @ V
        #pragma unroll
        for (int ks2 = 0; ks2 < 8; ks2++) {
            float2 lo = *(const float2*)&KP[wm + g][ks2 * 8 + 2 * kc];
            float2 hi = *(const float2*)&KP[wm + g + 8][ks2 * 8 + 2 * kc];
            const unsigned a0 = __float_as_uint(lo.x), a1 = __float_as_uint(hi.x);
            const unsigned a2 = __float_as_uint(lo.y), a3 = __float_as_uint(hi.y);
            #pragma unroll
            for (int nt = 0; nt < 8; nt++) {
                float2 vb = *(const float2*)&Vt[nt * 8 + g][ks2 * 8 + 2 * kc];
                MMA_TF32(oacc[nt], a0, a1, a2, a3,
                         __float_as_uint(vb.x), __float_as_uint(vb.y));
            }
        }
    }

    // ---- epilogue
    const float inv0 = 1.f / l0, inv1 = 1.f / l1;
    float* op0 = g_ctx + ((long)eb * S_ + qt * 64 + wm + g) * D_ + h * 64;
    float* op1 = op0 + 8L * D_;
    #pragma unroll
    for (int nt = 0; nt < 8; nt++) {
        float2 v0 = {oacc[nt][0] * inv0, oacc[nt][1] * inv0};
        float2 v1 = {oacc[nt][2] * inv1, oacc[nt][3] * inv1};
        *(float2*)(op0 + nt * 8 + c2k) = v0;
        *(float2*)(op1 + nt * 8 + c2k) = v1;
    }
}

// ---------------------------------------------------------------------------
// Partial seq-sums of ctx: grid (eb=64, chunk=8), deterministic two-stage mean.
// ---------------------------------------------------------------------------
__global__ __launch_bounds__(768)
void mean_ctx_kernel()
{
    const int eb = blockIdx.x;
    const int c  = blockIdx.y;
    const int d  = threadIdx.x;
    const float* p = g_ctx + ((long)eb * S_ + c * 64) * D_ + d;
    float s = 0.f;
    #pragma unroll 8
    for (int t = 0; t < 64; t++) s += p[(long)t * D_];
    g_mpart[((long)eb * 8 + c) * D_ + d] = s;
}

// ---------------------------------------------------------------------------
// feat[e,b,n] = mean_ctx[e,b,:] . Wd[e,n,:] + bd[e,n]   (== mean_s(att))
// ---------------------------------------------------------------------------
__global__ __launch_bounds__(256)
void featgemm_kernel(const float* __restrict__ Wd, const float* __restrict__ bd)
{
    const int e  = blockIdx.y;
    const int nc = blockIdx.x;
    const int tid = threadIdx.x, warp = tid >> 5, lane = tid & 31;

    __shared__ float mc[8][768];
    for (int i = tid; i < 8 * 768; i += 256) {
        const int b = i / 768, d = i % 768;
        const float* pp = g_mpart + ((long)(e * 8 + b) * 8) * D_ + d;
        float s = 0.f;
        #pragma unroll
        for (int c = 0; c < 8; c++) s += pp[c * D_];
        mc[b][d] = s * (1.0f / (float)S_);
    }
    __syncthreads();

    for (int rr = 0; rr < 16; rr++) {
        const int n = nc * 128 + warp * 16 + rr;
        const float* wp = Wd + ((long)e * D_ + n) * D_;
        float wreg[24];
        #pragma unroll
        for (int j = 0; j < 24; j++) wreg[j] = wp[lane + 32 * j];
        #pragma unroll
        for (int b = 0; b < 8; b++) {
            float s = 0.f;
            #pragma unroll
            for (int j = 0; j < 24; j++) s += wreg[j] * mc[b][lane + 32 * j];
            #pragma unroll
            for (int off = 16; off > 0; off >>= 1)
                s += __shfl_xor_sync(0xffffffffu, s, off);
            if (lane == 0)
                g_feat[(e * 8 + b) * D_ + n] = s + bd[e * D_ + n];
        }
    }
}

// ---------------------------------------------------------------------------
// sel[b] = argmin_e ||feat[e,b] - centers[e]||
// ---------------------------------------------------------------------------
__global__ __launch_bounds__(256)
void route_kernel(const float* __restrict__ centers)
{
    const int b = blockIdx.x, tid = threadIdx.x;
    __shared__ float red[256];
    float best = 3.4e38f;
    int   bi   = 0;
    for (int e = 0; e < E_; e++) {
        float s = 0.f;
        const float* fp = g_feat + (e * B_ + b) * D_;
        const float* cp = centers + e * D_;
        for (int d = tid; d < D_; d += 256) {
            float df = fp[d] - cp[d];
            s += df * df;
        }
        red[tid] = s; __syncthreads();
        for (int st = 128; st > 0; st >>= 1) {
            if (tid < st) red[tid] += red[tid + st];
            __syncthreads();
        }
        if (tid == 0 && red[0] < best) { best = red[0]; bi = e; }
        __syncthreads();
    }
    if (tid == 0) g_sel[b] = bi;
}

// ---------------------------------------------------------------------------
// h1 = LN(att_sel + x) * g1[sel] + b1[sel]
// ---------------------------------------------------------------------------
__global__ __launch_bounds__(256)
void add_ln1_kernel(const float* __restrict__ x,
                    const float* __restrict__ gma, const float* __restrict__ bta)
{
    const int t = blockIdx.x;           // b*512 + s
    const int b = t >> 9;
    const int e = g_sel[b];
    const int tid = threadIdx.x;
    const float* ap = g_att + (long)t * D_;
    const float* xp = x + (long)t * D_;
    __shared__ float red[256];

    float v0 = ap[tid]       + xp[tid];
    float v1 = ap[tid + 256] + xp[tid + 256];
    float v2 = ap[tid + 512] + xp[tid + 512];

    red[tid] = v0 + v1 + v2; __syncthreads();
    for (int st = 128; st > 0; st >>= 1) { if (tid < st) red[tid] += red[tid + st]; __syncthreads(); }
    const float mean = red[0] * (1.0f / (float)D_);
    __syncthreads();
    float d0 = v0 - mean, d1 = v1 - mean, d2 = v2 - mean;
    red[tid] = d0*d0 + d1*d1 + d2*d2; __syncthreads();
    for (int st = 128; st > 0; st >>= 1) { if (tid < st) red[tid] += red[tid + st]; __syncthreads(); }
    const float rstd = rsqrtf(red[0] * (1.0f / (float)D_) + 1e-12f);

    const float* g  = gma + e * D_;
    const float* bb = bta + e * D_;
    float* hp = g_h1 + (long)t * D_;
    hp[tid]       = d0 * rstd * g[tid]       + bb[tid];
    hp[tid + 256] = d1 * rstd * g[tid + 256] + bb[tid + 256];
    hp[tid + 512] = d2 * rstd * g[tid + 512] + bb[tid + 512];
}

// ---------------------------------------------------------------------------
// out = LN(h1 + ffn) * g2[sel] + b2[sel]
// ---------------------------------------------------------------------------
__global__ __launch_bounds__(256)
void ln2_kernel(const float* __restrict__ gma, const float* __restrict__ bta,
                float* __restrict__ out)
{
    const int t = blockIdx.x;
    const int b = t >> 9;
    const int e = g_sel[b];
    const int tid = threadIdx.x;
    const float* hp = g_h1  + (long)t * D_;
    const float* fp = g_ffn + (long)t * D_;
    __shared__ float red[256];

    float v0 = hp[tid]       + fp[tid];
    float v1 = hp[tid + 256] + fp[tid + 256];
    float v2 = hp[tid + 512] + fp[tid + 512];

    red[tid] = v0 + v1 + v2; __syncthreads();
    for (int st = 128; st > 0; st >>= 1) { if (tid < st) red[tid] += red[tid + st]; __syncthreads(); }
    const float mean = red[0] * (1.0f / (float)D_);
    __syncthreads();
    float d0 = v0 - mean, d1 = v1 - mean, d2 = v2 - mean;
    red[tid] = d0*d0 + d1*d1 + d2*d2; __syncthreads();
    for (int st = 128; st > 0; st >>= 1) { if (tid < st) red[tid] += red[tid + st]; __syncthreads(); }
    const float rstd = rsqrtf(red[0] * (1.0f / (float)D_) + 1e-12f);

    const float* g  = gma + e * D_;
    const float* bb = bta + e * D_;
    float* op = out + (long)t * D_;
    op[tid]       = d0 * rstd * g[tid]       + bb[tid];
    op[tid + 256] = d1 * rstd * g[tid + 256] + bb[tid + 256];
    op[tid + 512] = d2 * rstd * g[tid + 512] + bb[tid + 512];
}

// ---------------------------------------------------------------------------
extern "C" void kernel_launch(void* const* d_in, const int* in_sizes, int n_in,
                              void* d_out, int out_size)
{
    const float* x       = (const float*)d_in[0];
    const int*   mask    = (const int*)  d_in[1];
    const float* Wqkv    = (const float*)d_in[2];
    const float* Wd      = (const float*)d_in[3];
    const float* bd      = (const float*)d_in[4];
    const float* ln1g    = (const float*)d_in[5];
    const float* ln1b    = (const float*)d_in[6];
    const float* W1      = (const float*)d_in[7];
    const float* b1      = (const float*)d_in[8];
    const float* W2      = (const float*)d_in[9];
    const float* b2      = (const float*)d_in[10];
    const float* ln2g    = (const float*)d_in[11];
    const float* ln2b    = (const float*)d_in[12];
    const float* centers = (const float*)d_in[13];
    float* out = (float*)d_out;

    float *qkvp, *ctxp, *attp, *h1p, *midp, *ffnp;
    int* selp;
    cudaGetSymbolAddress((void**)&qkvp, g_qkv);
    cudaGetSymbolAddress((void**)&ctxp, g_ctx);
    cudaGetSymbolAddress((void**)&attp, g_att);
    cudaGetSymbolAddress((void**)&h1p,  g_h1);
    cudaGetSymbolAddress((void**)&midp, g_mid);
    cudaGetSymbolAddress((void**)&ffnp, g_ffn);
    cudaGetSymbolAddress((void**)&selp, g_sel);

    const int M = B_ * S_;   // 4096

    // 1. QKV for all experts: (4096 x 768) x (2304 x 768)^T per e
    mma_gemm<false, false><<<dim3(QKVW / 128, M / 128, E_), 256>>>(
        x, Wqkv, nullptr, qkvp, M, QKVW, D_,
        0L, 0L, (long)QKVW * D_, 0L, (long)M * QKVW, nullptr);

    // 2. Attention for all (e,b,h) on tensor cores
    attn_mma_kernel<<<dim3(S_ / 64, H_, E_ * B_), 128>>>(mask);

    // 3. routing: partial seq-sums -> feat (tiny GEMM) -> argmin
    mean_ctx_kernel<<<dim3(E_ * B_, 8), 768>>>();
    featgemm_kernel<<<dim3(D_ / 128, E_), 256>>>(Wd, bd);
    route_kernel<<<B_, 256>>>(centers);

    // 4. attention.dense ONLY for selected expert: per b, (512 x 768) x Wd[sel]^T
    mma_gemm<false, true><<<dim3(D_ / 128, S_ / 128, B_), 256>>>(
        ctxp, Wd, bd, attp, S_, D_, D_,
        (long)S_ * D_, (long)B_ * S_ * D_, (long)D_ * D_, (long)D_,
        (long)S_ * D_, selp);

    // 5. post-attention LN (selected expert only)
    add_ln1_kernel<<<M, 256>>>(x, ln1g, ln1b);

    // 6. FFN (selected expert only): gelu(h1 @ W1^T + b1)
    mma_gemm<true, true><<<dim3(DFF_ / 128, S_ / 128, B_), 256>>>(
        h1p, W1, b1, midp, S_, DFF_, D_,
        (long)S_ * D_, 0L, (long)DFF_ * D_, (long)DFF_, (long)S_ * DFF_, selp);

    // 7. mid @ W2^T + b2
    mma_gemm<false, true><<<dim3(D_ / 128, S_ / 128, B_), 256>>>(
        midp, W2, b2, ffnp, S_, D_, DFF_,
        (long)S_ * DFF_, 0L, (long)D_ * DFF_, (long)D_, (long)S_ * D_, selp);

    // 8. final LN -> output
    ln2_kernel<<<M, 256>>>(ln2g, ln2b, out);
}

// round 15
// speedup vs baseline: 3.0167x; 1.0564x over previous
#include <cuda_runtime.h>
#include <math.h>

// Problem dims (fixed by the dataset)
#define E_   8
#define B_   8
#define S_   512
#define D_   768
#define H_   12
#define DH_  64
#define DFF_ 3072
#define QKVW 2304   // H_ * 3 * DH_

#define SCALE_F 0.036084391824351615f   // D_^-0.5

// Dynamic smem for the GEMM: As[2][128][20] + Bs[2][256][20] floats
#define GEMM_SMEM_FLOATS (2 * 128 * 20 + 2 * 256 * 20)
#define GEMM_SMEM_BYTES  (GEMM_SMEM_FLOATS * 4)

// ---------------------------------------------------------------------------
// Scratch: __device__ globals (no cudaMalloc allowed)
// ---------------------------------------------------------------------------
static __device__ float g_qkv [(size_t)E_ * B_ * S_ * QKVW];  // [e][b*S+s][h*192+k]
static __device__ float g_ctx [(size_t)E_ * B_ * S_ * D_];    // [e][t][h*64+d]
static __device__ float g_mpart[(size_t)E_ * B_ * 8 * D_];    // partial seq-sums of ctx
static __device__ float g_att [(size_t)B_ * S_ * D_];         // dense out, SELECTED expert
static __device__ float g_feat[E_ * B_ * D_];
static __device__ int   g_sel[B_];
static __device__ float g_h1 [(size_t)B_ * S_ * D_];
static __device__ float g_mid[(size_t)B_ * S_ * DFF_];
static __device__ float g_ffn[(size_t)B_ * S_ * D_];

// ---------------------------------------------------------------------------
// mma.tf32 consumes raw fp32 register bits (HW truncates the low mantissa).
// ---------------------------------------------------------------------------
#define MMA_TF32(d, a0, a1, a2, a3, b0, b1)                                   \
    asm volatile("mma.sync.aligned.m16n8k8.row.col.f32.tf32.tf32.f32 "        \
                 "{%0,%1,%2,%3}, {%4,%5,%6,%7}, {%8,%9}, {%0,%1,%2,%3};"      \
                 : "+f"(d[0]), "+f"(d[1]), "+f"(d[2]), "+f"(d[3])             \
                 : "r"(a0), "r"(a1), "r"(a2), "r"(a3), "r"(b0), "r"(b1));

// ---------------------------------------------------------------------------
// Tensor-core GEMM: C = A * W^T (+bias)(+gelu), tf32 mma / fp32 accum.
// CTA tile 128x256x16, 256 threads = 8 warps of 64x64 (4x8 m16n8 tiles each):
// per k-step 16 LDS.64 feed 32 mmas (2.0 mma/LDS). 2-stage double buffer,
// register prefetch, one __syncthreads per k-iter.
// Smem: m-major, k-interleaved: phys(k) = (k&8) | ((k&3)<<1) | ((k>>2)&1)
// with pitch 20 (conflict-free across 8 consecutive rows).
// ---------------------------------------------------------------------------
template<bool GELU, bool HASBIAS>
__global__ __launch_bounds__(256)
void mma_gemm(const float* __restrict__ A, const float* __restrict__ W,
              const float* __restrict__ bias, float* __restrict__ C,
              int M, int N, int K,
              long Az, long Asel, long Wz, long biasz, long Cz,
              const int* __restrict__ sel)
{
    const int z = blockIdx.z;
    const int w = sel ? sel[z] : z;
    A += (long)z * Az + (sel ? (long)w * Asel : 0L);
    W += (long)w * Wz;
    if (HASBIAS) bias += (long)w * biasz;
    C += (long)z * Cz;

    extern __shared__ float sm[];
    float (*As)[128][20] = (float(*)[128][20])sm;                 // [stage][m][phys_k]
    float (*Bs)[256][20] = (float(*)[256][20])(sm + 2 * 128 * 20); // [stage][n][phys_k]

    const int tid  = threadIdx.x;
    const int m0   = blockIdx.y * 128;
    const int n0   = blockIdx.x * 256;
    const int warp = tid >> 5;
    const int lane = tid & 31;
    const int wm   = (warp & 1) * 64;     // warp row offset
    const int wn   = (warp >> 1) * 64;    // warp col offset
    const int g    = lane >> 2;           // groupID   0..7
    const int kc   = lane & 3;            // tid-in-grp 0..3

    float acc[4][8][4];
    #pragma unroll
    for (int i = 0; i < 4; i++)
        #pragma unroll
        for (int j = 0; j < 8; j++)
            #pragma unroll
            for (int q = 0; q < 4; q++) acc[i][j][q] = 0.f;

    const int lc = (tid & 3) * 4;    // k offset of this thread's float4
    const int lr = tid >> 2;         // row 0..63
    int pc[4];
    #pragma unroll
    for (int q = 0; q < 4; q++) {
        int k = lc + q;
        pc[q] = (k & 8) | ((k & 3) << 1) | ((k >> 2) & 1);
    }

    float4 va[2], vb[4];
    #pragma unroll
    for (int i = 0; i < 2; i++)
        va[i] = *(const float4*)&A[(long)(m0 + lr + i * 64) * K + lc];
    #pragma unroll
    for (int i = 0; i < 4; i++)
        vb[i] = *(const float4*)&W[(long)(n0 + lr + i * 64) * K + lc];

    #pragma unroll
    for (int i = 0; i < 2; i++) {
        const int r = lr + i * 64;
        As[0][r][pc[0]] = va[i].x; As[0][r][pc[1]] = va[i].y;
        As[0][r][pc[2]] = va[i].z; As[0][r][pc[3]] = va[i].w;
    }
    #pragma unroll
    for (int i = 0; i < 4; i++) {
        const int r = lr + i * 64;
        Bs[0][r][pc[0]] = vb[i].x; Bs[0][r][pc[1]] = vb[i].y;
        Bs[0][r][pc[2]] = vb[i].z; Bs[0][r][pc[3]] = vb[i].w;
    }
    __syncthreads();

    for (int k0 = 0; k0 < K; k0 += 16) {
        const int st    = (k0 >> 4) & 1;
        const bool more = (k0 + 16 < K);

        if (more) {   // prefetch next tile into registers (overlaps mma)
            #pragma unroll
            for (int i = 0; i < 2; i++)
                va[i] = *(const float4*)&A[(long)(m0 + lr + i * 64) * K + k0 + 16 + lc];
            #pragma unroll
            for (int i = 0; i < 4; i++)
                vb[i] = *(const float4*)&W[(long)(n0 + lr + i * 64) * K + k0 + 16 + lc];
        }

        #pragma unroll
        for (int ks = 0; ks < 2; ks++) {
            const int kb = ks * 8 + 2 * kc;
            unsigned af[4][4], bf[8][2];
            #pragma unroll
            for (int i = 0; i < 4; i++) {
                const int r = wm + i * 16 + g;
                float2 a02 = *(const float2*)&As[st][r][kb];
                float2 a13 = *(const float2*)&As[st][r + 8][kb];
                af[i][0] = __float_as_uint(a02.x);
                af[i][1] = __float_as_uint(a13.x);
                af[i][2] = __float_as_uint(a02.y);
                af[i][3] = __float_as_uint(a13.y);
            }
            #pragma unroll
            for (int j = 0; j < 8; j++) {
                const int c = wn + j * 8 + g;
                float2 b01 = *(const float2*)&Bs[st][c][kb];
                bf[j][0] = __float_as_uint(b01.x);
                bf[j][1] = __float_as_uint(b01.y);
            }
            #pragma unroll
            for (int i = 0; i < 4; i++)
                #pragma unroll
                for (int j = 0; j < 8; j++)
                    MMA_TF32(acc[i][j], af[i][0], af[i][1], af[i][2], af[i][3],
                             bf[j][0], bf[j][1]);
        }

        if (more) {   // store prefetched tile into the other stage
            const int so = st ^ 1;
            #pragma unroll
            for (int i = 0; i < 2; i++) {
                const int r = lr + i * 64;
                As[so][r][pc[0]] = va[i].x; As[so][r][pc[1]] = va[i].y;
                As[so][r][pc[2]] = va[i].z; As[so][r][pc[3]] = va[i].w;
            }
            #pragma unroll
            for (int i = 0; i < 4; i++) {
                const int r = lr + i * 64;
                Bs[so][r][pc[0]] = vb[i].x; Bs[so][r][pc[1]] = vb[i].y;
                Bs[so][r][pc[2]] = vb[i].z; Bs[so][r][pc[3]] = vb[i].w;
            }
        }
        __syncthreads();
    }

    #pragma unroll
    for (int i = 0; i < 4; i++) {
        const long row0 = m0 + wm + i * 16 + g;
        #pragma unroll
        for (int j = 0; j < 8; j++) {
            const int col = n0 + wn + j * 8 + 2 * kc;
            float v0 = acc[i][j][0], v1 = acc[i][j][1];
            float v2 = acc[i][j][2], v3 = acc[i][j][3];
            if (HASBIAS) {
                float bb0 = bias[col], bb1 = bias[col + 1];
                v0 += bb0; v1 += bb1; v2 += bb0; v3 += bb1;
            }
            if (GELU) {
                v0 = 0.5f * v0 * (1.0f + erff(v0 * 0.7071067811865476f));
                v1 = 0.5f * v1 * (1.0f + erff(v1 * 0.7071067811865476f));
                v2 = 0.5f * v2 * (1.0f + erff(v2 * 0.7071067811865476f));
                v3 = 0.5f * v3 * (1.0f + erff(v3 * 0.7071067811865476f));
            }
            float2 lo = {v0, v1}, hi = {v2, v3};
            *(float2*)&C[row0 * N + col]       = lo;
            *(float2*)&C[(row0 + 8) * N + col] = hi;
        }
    }
}

// ---------------------------------------------------------------------------
// Tensor-core flash attention. Block = (qt 64 rows, h, eb). 128 threads,
// 4 warps x m16. Raw fp32 bits feed the tf32 mma (HW truncates).
// ---------------------------------------------------------------------------
#define AP 76   // smem pitch

__global__ __launch_bounds__(128)
void attn_mma_kernel(const int* __restrict__ mask)
{
    const int qt  = blockIdx.x;        // 0..7
    const int h   = blockIdx.y;        // 0..11
    const int eb  = blockIdx.z;        // e*8 + b
    const int b   = eb & 7;
    const int tid = threadIdx.x;
    const int warp = tid >> 5, lane = tid & 31;
    const int g = lane >> 2, kc = lane & 3;
    const int wm = warp * 16;

    const long rowbase = (long)eb * S_ * QKVW + h * 192;

    __shared__ float KP[64][AP];   // K tile, then P tile (lifetimes disjoint)
    __shared__ float Vt[64][AP];   // transposed V: [dh][phys(key)]
    __shared__ float sbias[64];

    const int lrow = tid >> 1;        // loader row 0..63
    const int lc0  = (tid & 1) * 32;  // loader column half

    // ---- stage Q (scaled) into KP, build A-fragments in registers
    {
        const float* qp = g_qkv + rowbase + (long)(qt * 64 + lrow) * QKVW + lc0;
        #pragma unroll
        for (int i = 0; i < 8; i++) {
            float4 v = *(const float4*)(qp + 4 * i);
            const int d  = lc0 + 4 * i;
            const int pb = (d & ~7) | ((d >> 2) & 1);
            KP[lrow][pb + 0] = v.x * SCALE_F;
            KP[lrow][pb + 2] = v.y * SCALE_F;
            KP[lrow][pb + 4] = v.z * SCALE_F;
            KP[lrow][pb + 6] = v.w * SCALE_F;
        }
    }
    __syncthreads();

    unsigned qf[8][4];
    #pragma unroll
    for (int ks = 0; ks < 8; ks++) {
        float2 lo = *(const float2*)&KP[wm + g][ks * 8 + 2 * kc];
        float2 hi = *(const float2*)&KP[wm + g + 8][ks * 8 + 2 * kc];
        qf[ks][0] = __float_as_uint(lo.x);
        qf[ks][1] = __float_as_uint(hi.x);
        qf[ks][2] = __float_as_uint(lo.y);
        qf[ks][3] = __float_as_uint(hi.y);
    }

    float oacc[8][4];
    #pragma unroll
    for (int nt = 0; nt < 8; nt++)
        #pragma unroll
        for (int q = 0; q < 4; q++) oacc[nt][q] = 0.f;
    float m0 = -1e30f, m1 = -1e30f, l0 = 0.f, l1 = 0.f;

    const int c2k   = 2 * kc;
    const int pcol0 = ((c2k & 3) << 1) | ((c2k >> 2) & 1);
    const int pcol1 = (((c2k + 1) & 3) << 1) | (((c2k + 1) >> 2) & 1);
    const int pkey  = (lrow & ~7) | ((lrow & 3) << 1) | ((lrow >> 2) & 1);

    for (int kt = 0; kt < 8; kt++) {
        __syncthreads();   // previous users of KP / Vt are done
        {
            const float* kp = g_qkv + rowbase + (long)(kt * 64 + lrow) * QKVW + 64 + lc0;
            const float* vp = kp + 64;
            #pragma unroll
            for (int i = 0; i < 8; i++) {
                float4 kv = *(const float4*)(kp + 4 * i);
                const int d  = lc0 + 4 * i;
                const int pb = (d & ~7) | ((d >> 2) & 1);
                KP[lrow][pb + 0] = kv.x;
                KP[lrow][pb + 2] = kv.y;
                KP[lrow][pb + 4] = kv.z;
                KP[lrow][pb + 6] = kv.w;
                float4 vv = *(const float4*)(vp + 4 * i);
                Vt[d + 0][pkey] = vv.x;
                Vt[d + 1][pkey] = vv.y;
                Vt[d + 2][pkey] = vv.z;
                Vt[d + 3][pkey] = vv.w;
            }
            if (tid < 64)
                sbias[tid] = (mask[b * S_ + kt * 64 + tid] == 0) ? -1e30f : 0.f;
        }
        __syncthreads();

        // ---- scores S = Q @ K^T
        float sacc[8][4];
        #pragma unroll
        for (int nt = 0; nt < 8; nt++) {
            #pragma unroll
            for (int q = 0; q < 4; q++) sacc[nt][q] = 0.f;
            #pragma unroll
            for (int ks = 0; ks < 8; ks++) {
                float2 bb = *(const float2*)&KP[nt * 8 + g][ks * 8 + 2 * kc];
                MMA_TF32(sacc[nt], qf[ks][0], qf[ks][1], qf[ks][2], qf[ks][3],
                         __float_as_uint(bb.x), __float_as_uint(bb.y));
            }
        }

        // ---- mask + online softmax
        float mx0 = -1e30f, mx1 = -1e30f;
        #pragma unroll
        for (int nt = 0; nt < 8; nt++) {
            float b0 = sbias[nt * 8 + c2k], b1 = sbias[nt * 8 + c2k + 1];
            sacc[nt][0] += b0; sacc[nt][1] += b1;
            sacc[nt][2] += b0; sacc[nt][3] += b1;
            mx0 = fmaxf(mx0, fmaxf(sacc[nt][0], sacc[nt][1]));
            mx1 = fmaxf(mx1, fmaxf(sacc[nt][2], sacc[nt][3]));
        }
        mx0 = fmaxf(mx0, __shfl_xor_sync(0xffffffffu, mx0, 1));
        mx0 = fmaxf(mx0, __shfl_xor_sync(0xffffffffu, mx0, 2));
        mx1 = fmaxf(mx1, __shfl_xor_sync(0xffffffffu, mx1, 1));
        mx1 = fmaxf(mx1, __shfl_xor_sync(0xffffffffu, mx1, 2));
        const float mn0 = fmaxf(m0, mx0), mn1 = fmaxf(m1, mx1);
        const float cr0 = __expf(m0 - mn0), cr1 = __expf(m1 - mn1);
        m0 = mn0; m1 = mn1;

        float ll0 = 0.f, ll1 = 0.f;
        #pragma unroll
        for (int nt = 0; nt < 8; nt++) {
            sacc[nt][0] = __expf(sacc[nt][0] - mn0);
            sacc[nt][1] = __expf(sacc[nt][1] - mn0);
            sacc[nt][2] = __expf(sacc[nt][2] - mn1);
            sacc[nt][3] = __expf(sacc[nt][3] - mn1);
            ll0 += sacc[nt][0] + sacc[nt][1];
            ll1 += sacc[nt][2] + sacc[nt][3];
        }
        ll0 += __shfl_xor_sync(0xffffffffu, ll0, 1);
        ll0 += __shfl_xor_sync(0xffffffffu, ll0, 2);
        ll1 += __shfl_xor_sync(0xffffffffu, ll1, 1);
        ll1 += __shfl_xor_sync(0xffffffffu, ll1, 2);
        l0 = l0 * cr0 + ll0;
        l1 = l1 * cr1 + ll1;
        #pragma unroll
        for (int nt = 0; nt < 8; nt++) {
            oacc[nt][0] *= cr0; oacc[nt][1] *= cr0;
            oacc[nt][2] *= cr1; oacc[nt][3] *= cr1;
        }

        __syncthreads();   // all warps finished reading K from KP
        #pragma unroll
        for (int nt = 0; nt < 8; nt++) {
            KP[wm + g][nt * 8 + pcol0]     = sacc[nt][0];
            KP[wm + g][nt * 8 + pcol1]     = sacc[nt][1];
            KP[wm + g + 8][nt * 8 + pcol0] = sacc[nt][2];
            KP[wm + g + 8][nt * 8 + pcol1] = sacc[nt][3];
        }
        __syncwarp();

        // ---- O += P @ V
        #pragma unroll
        for (int ks2 = 0; ks2 < 8; ks2++) {
            float2 lo = *(const float2*)&KP[wm + g][ks2 * 8 + 2 * kc];
            float2 hi = *(const float2*)&KP[wm + g + 8][ks2 * 8 + 2 * kc];
            const unsigned a0 = __float_as_uint(lo.x), a1 = __float_as_uint(hi.x);
            const unsigned a2 = __float_as_uint(lo.y), a3 = __float_as_uint(hi.y);
            #pragma unroll
            for (int nt = 0; nt < 8; nt++) {
                float2 vb = *(const float2*)&Vt[nt * 8 + g][ks2 * 8 + 2 * kc];
                MMA_TF32(oacc[nt], a0, a1, a2, a3,
                         __float_as_uint(vb.x), __float_as_uint(vb.y));
            }
        }
    }

    // ---- epilogue
    const float inv0 = 1.f / l0, inv1 = 1.f / l1;
    float* op0 = g_ctx + ((long)eb * S_ + qt * 64 + wm + g) * D_ + h * 64;
    float* op1 = op0 + 8L * D_;
    #pragma unroll
    for (int nt = 0; nt < 8; nt++) {
        float2 v0 = {oacc[nt][0] * inv0, oacc[nt][1] * inv0};
        float2 v1 = {oacc[nt][2] * inv1, oacc[nt][3] * inv1};
        *(float2*)(op0 + nt * 8 + c2k) = v0;
        *(float2*)(op1 + nt * 8 + c2k) = v1;
    }
}

// ---------------------------------------------------------------------------
// Partial seq-sums of ctx: grid (eb=64, chunk=8), deterministic two-stage mean.
// ---------------------------------------------------------------------------
__global__ __launch_bounds__(768)
void mean_ctx_kernel()
{
    const int eb = blockIdx.x;
    const int c  = blockIdx.y;
    const int d  = threadIdx.x;
    const float* p = g_ctx + ((long)eb * S_ + c * 64) * D_ + d;
    float s = 0.f;
    #pragma unroll 8
    for (int t = 0; t < 64; t++) s += p[(long)t * D_];
    g_mpart[((long)eb * 8 + c) * D_ + d] = s;
}

// ---------------------------------------------------------------------------
// feat[e,b,n] = mean_ctx[e,b,:] . Wd[e,n,:] + bd[e,n]   (== mean_s(att))
// ---------------------------------------------------------------------------
__global__ __launch_bounds__(256)
void featgemm_kernel(const float* __restrict__ Wd, const float* __restrict__ bd)
{
    const int e  = blockIdx.y;
    const int nc = blockIdx.x;
    const int tid = threadIdx.x, warp = tid >> 5, lane = tid & 31;

    __shared__ float mc[8][768];
    for (int i = tid; i < 8 * 768; i += 256) {
        const int b = i / 768, d = i % 768;
        const float* pp = g_mpart + ((long)(e * 8 + b) * 8) * D_ + d;
        float s = 0.f;
        #pragma unroll
        for (int c = 0; c < 8; c++) s += pp[c * D_];
        mc[b][d] = s * (1.0f / (float)S_);
    }
    __syncthreads();

    for (int rr = 0; rr < 16; rr++) {
        const int n = nc * 128 + warp * 16 + rr;
        const float* wp = Wd + ((long)e * D_ + n) * D_;
        float wreg[24];
        #pragma unroll
        for (int j = 0; j < 24; j++) wreg[j] = wp[lane + 32 * j];
        #pragma unroll
        for (int b = 0; b < 8; b++) {
            float s = 0.f;
            #pragma unroll
            for (int j = 0; j < 24; j++) s += wreg[j] * mc[b][lane + 32 * j];
            #pragma unroll
            for (int off = 16; off > 0; off >>= 1)
                s += __shfl_xor_sync(0xffffffffu, s, off);
            if (lane == 0)
                g_feat[(e * 8 + b) * D_ + n] = s + bd[e * D_ + n];
        }
    }
}

// ---------------------------------------------------------------------------
// sel[b] = argmin_e ||feat[e,b] - centers[e]||
// ---------------------------------------------------------------------------
__global__ __launch_bounds__(256)
void route_kernel(const float* __restrict__ centers)
{
    const int b = blockIdx.x, tid = threadIdx.x;
    __shared__ float red[256];
    float best = 3.4e38f;
    int   bi   = 0;
    for (int e = 0; e < E_; e++) {
        float s = 0.f;
        const float* fp = g_feat + (e * B_ + b) * D_;
        const float* cp = centers + e * D_;
        for (int d = tid; d < D_; d += 256) {
            float df = fp[d] - cp[d];
            s += df * df;
        }
        red[tid] = s; __syncthreads();
        for (int st = 128; st > 0; st >>= 1) {
            if (tid < st) red[tid] += red[tid + st];
            __syncthreads();
        }
        if (tid == 0 && red[0] < best) { best = red[0]; bi = e; }
        __syncthreads();
    }
    if (tid == 0) g_sel[b] = bi;
}

// ---------------------------------------------------------------------------
// h1 = LN(att_sel + x) * g1[sel] + b1[sel]
// ---------------------------------------------------------------------------
__global__ __launch_bounds__(256)
void add_ln1_kernel(const float* __restrict__ x,
                    const float* __restrict__ gma, const float* __restrict__ bta)
{
    const int t = blockIdx.x;           // b*512 + s
    const int b = t >> 9;
    const int e = g_sel[b];
    const int tid = threadIdx.x;
    const float* ap = g_att + (long)t * D_;
    const float* xp = x + (long)t * D_;
    __shared__ float red[256];

    float v0 = ap[tid]       + xp[tid];
    float v1 = ap[tid + 256] + xp[tid + 256];
    float v2 = ap[tid + 512] + xp[tid + 512];

    red[tid] = v0 + v1 + v2; __syncthreads();
    for (int st = 128; st > 0; st >>= 1) { if (tid < st) red[tid] += red[tid + st]; __syncthreads(); }
    const float mean = red[0] * (1.0f / (float)D_);
    __syncthreads();
    float d0 = v0 - mean, d1 = v1 - mean, d2 = v2 - mean;
    red[tid] = d0*d0 + d1*d1 + d2*d2; __syncthreads();
    for (int st = 128; st > 0; st >>= 1) { if (tid < st) red[tid] += red[tid + st]; __syncthreads(); }
    const float rstd = rsqrtf(red[0] * (1.0f / (float)D_) + 1e-12f);

    const float* g  = gma + e * D_;
    const float* bb = bta + e * D_;
    float* hp = g_h1 + (long)t * D_;
    hp[tid]       = d0 * rstd * g[tid]       + bb[tid];
    hp[tid + 256] = d1 * rstd * g[tid + 256] + bb[tid + 256];
    hp[tid + 512] = d2 * rstd * g[tid + 512] + bb[tid + 512];
}

// ---------------------------------------------------------------------------
// out = LN(h1 + ffn) * g2[sel] + b2[sel]
// ---------------------------------------------------------------------------
__global__ __launch_bounds__(256)
void ln2_kernel(const float* __restrict__ gma, const float* __restrict__ bta,
                float* __restrict__ out)
{
    const int t = blockIdx.x;
    const int b = t >> 9;
    const int e = g_sel[b];
    const int tid = threadIdx.x;
    const float* hp = g_h1  + (long)t * D_;
    const float* fp = g_ffn + (long)t * D_;
    __shared__ float red[256];

    float v0 = hp[tid]       + fp[tid];
    float v1 = hp[tid + 256] + fp[tid + 256];
    float v2 = hp[tid + 512] + fp[tid + 512];

    red[tid] = v0 + v1 + v2; __syncthreads();
    for (int st = 128; st > 0; st >>= 1) { if (tid < st) red[tid] += red[tid + st]; __syncthreads(); }
    const float mean = red[0] * (1.0f / (float)D_);
    __syncthreads();
    float d0 = v0 - mean, d1 = v1 - mean, d2 = v2 - mean;
    red[tid] = d0*d0 + d1*d1 + d2*d2; __syncthreads();
    for (int st = 128; st > 0; st >>= 1) { if (tid < st) red[tid] += red[tid + st]; __syncthreads(); }
    const float rstd = rsqrtf(red[0] * (1.0f / (float)D_) + 1e-12f);

    const float* g  = gma + e * D_;
    const float* bb = bta + e * D_;
    float* op = out + (long)t * D_;
    op[tid]       = d0 * rstd * g[tid]       + bb[tid];
    op[tid + 256] = d1 * rstd * g[tid + 256] + bb[tid + 256];
    op[tid + 512] = d2 * rstd * g[tid + 512] + bb[tid + 512];
}

// ---------------------------------------------------------------------------
extern "C" void kernel_launch(void* const* d_in, const int* in_sizes, int n_in,
                              void* d_out, int out_size)
{
    const float* x       = (const float*)d_in[0];
    const int*   mask    = (const int*)  d_in[1];
    const float* Wqkv    = (const float*)d_in[2];
    const float* Wd      = (const float*)d_in[3];
    const float* bd      = (const float*)d_in[4];
    const float* ln1g    = (const float*)d_in[5];
    const float* ln1b    = (const float*)d_in[6];
    const float* W1      = (const float*)d_in[7];
    const float* b1      = (const float*)d_in[8];
    const float* W2      = (const float*)d_in[9];
    const float* b2      = (const float*)d_in[10];
    const float* ln2g    = (const float*)d_in[11];
    const float* ln2b    = (const float*)d_in[12];
    const float* centers = (const float*)d_in[13];
    float* out = (float*)d_out;

    float *qkvp, *ctxp, *attp, *h1p, *midp, *ffnp;
    int* selp;
    cudaGetSymbolAddress((void**)&qkvp, g_qkv);
    cudaGetSymbolAddress((void**)&ctxp, g_ctx);
    cudaGetSymbolAddress((void**)&attp, g_att);
    cudaGetSymbolAddress((void**)&h1p,  g_h1);
    cudaGetSymbolAddress((void**)&midp, g_mid);
    cudaGetSymbolAddress((void**)&ffnp, g_ffn);
    cudaGetSymbolAddress((void**)&selp, g_sel);

    // opt-in to >48KB dynamic smem (idempotent; capture-safe: not a stream op)
    cudaFuncSetAttribute(mma_gemm<false, false>,
                         cudaFuncAttributeMaxDynamicSharedMemorySize, GEMM_SMEM_BYTES);
    cudaFuncSetAttribute(mma_gemm<false, true>,
                         cudaFuncAttributeMaxDynamicSharedMemorySize, GEMM_SMEM_BYTES);
    cudaFuncSetAttribute(mma_gemm<true, true>,
                         cudaFuncAttributeMaxDynamicSharedMemorySize, GEMM_SMEM_BYTES);

    const int M = B_ * S_;   // 4096

    // 1. QKV for all experts: (4096 x 768) x (2304 x 768)^T per e
    mma_gemm<false, false><<<dim3(QKVW / 256, M / 128, E_), 256, GEMM_SMEM_BYTES>>>(
        x, Wqkv, nullptr, qkvp, M, QKVW, D_,
        0L, 0L, (long)QKVW * D_, 0L, (long)M * QKVW, nullptr);

    // 2. Attention for all (e,b,h) on tensor cores
    attn_mma_kernel<<<dim3(S_ / 64, H_, E_ * B_), 128>>>(mask);

    // 3. routing: partial seq-sums -> feat (tiny GEMM) -> argmin
    mean_ctx_kernel<<<dim3(E_ * B_, 8), 768>>>();
    featgemm_kernel<<<dim3(D_ / 128, E_), 256>>>(Wd, bd);
    route_kernel<<<B_, 256>>>(centers);

    // 4. attention.dense ONLY for selected expert: per b, (512 x 768) x Wd[sel]^T
    mma_gemm<false, true><<<dim3(D_ / 256, S_ / 128, B_), 256, GEMM_SMEM_BYTES>>>(
        ctxp, Wd, bd, attp, S_, D_, D_,
        (long)S_ * D_, (long)B_ * S_ * D_, (long)D_ * D_, (long)D_,
        (long)S_ * D_, selp);

    // 5. post-attention LN (selected expert only)
    add_ln1_kernel<<<M, 256>>>(x, ln1g, ln1b);

    // 6. FFN (selected expert only): gelu(h1 @ W1^T + b1)
    mma_gemm<true, true><<<dim3(DFF_ / 256, S_ / 128, B_), 256, GEMM_SMEM_BYTES>>>(
        h1p, W1, b1, midp, S_, DFF_, D_,
        (long)S_ * D_, 0L, (long)DFF_ * D_, (long)DFF_, (long)S_ * DFF_, selp);

    // 7. mid @ W2^T + b2
    mma_gemm<false, true><<<dim3(D_ / 256, S_ / 128, B_), 256, GEMM_SMEM_BYTES>>>(
        midp, W2, b2, ffnp, S_, D_, DFF_,
        (long)S_ * DFF_, 0L, (long)D_ * DFF_, (long)D_, (long)S_ * D_, selp);

    // 8. final LN -> output
    ln2_kernel<<<M, 256>>>(ln2g, ln2b, out);
}